// round 1
// baseline (speedup 1.0000x reference)
#include <cuda_runtime.h>
#include <cuda_bf16.h>
#include <math.h>

// ---------------------------------------------------------------------------
// Problem constants
// ---------------------------------------------------------------------------
#define BB 4
#define TT 196
#define LTOT 392            // TM + T
#define DMODEL 1024
#define DINNER 2048
#define DSTATE 16
#define DCONV 4
#define DTRANK 64
#define NROWS (BB*LTOT)     // 1568
#define NOUT  (BB*TT)       // 784

// ---------------------------------------------------------------------------
// Device scratch (static: no allocations allowed)
// ---------------------------------------------------------------------------
__device__ float g_temb[BB * 1024];
__device__ float g_h   [BB * 2048];
__device__ float g_embt[BB * 1024];
__device__ float g_seq [NROWS * DMODEL];   // LN'ed concat sequence
__device__ float g_xn  [NROWS * DMODEL];   // rms_norm(seq)
__device__ float g_xz  [NROWS * (2*DINNER)]; // in_proj out: [.,4096]
__device__ float g_xc  [NROWS * DINNER];   // silu(conv(x))
__device__ float g_dbc [NROWS * 96];       // x_proj out (dt|B|C)
__device__ float g_dlt [NROWS * DINNER];   // softplus(dt_proj)
__device__ float g_yc  [NOUT * DINNER];    // scan out, compact l>=196
__device__ float g_mo  [NOUT * DMODEL];    // out_proj result

// ---------------------------------------------------------------------------
// Helpers
// ---------------------------------------------------------------------------
__device__ __forceinline__ float siluf(float x) {
    return x / (1.0f + __expf(-x));
}

__device__ __forceinline__ void blockReduce2(float& a, float& b) {
    __shared__ float s[66];
    #pragma unroll
    for (int o = 16; o; o >>= 1) {
        a += __shfl_xor_sync(0xFFFFFFFFu, a, o);
        b += __shfl_xor_sync(0xFFFFFFFFu, b, o);
    }
    int w = threadIdx.x >> 5, lane = threadIdx.x & 31;
    if (lane == 0) { s[w] = a; s[32 + w] = b; }
    __syncthreads();
    if (threadIdx.x == 0) {
        float sa = 0.f, sb = 0.f;
        int nw = blockDim.x >> 5;
        for (int i = 0; i < nw; i++) { sa += s[i]; sb += s[32 + i]; }
        s[64] = sa; s[65] = sb;
    }
    __syncthreads();
    a = s[64]; b = s[65];
    __syncthreads();
}

// ---------------------------------------------------------------------------
// 1. timestep embedding
// ---------------------------------------------------------------------------
__global__ void k_temb(const int* __restrict__ ts) {
    int b = blockIdx.x;
    int i = threadIdx.x;                // 0..511
    float t = (float)ts[b];
    float freq = __expf(-9.210340371976184f * (float)i / 512.0f);
    float arg = t * freq;
    g_temb[b * 1024 + i]       = cosf(arg);
    g_temb[b * 1024 + 512 + i] = sinf(arg);
}

// ---------------------------------------------------------------------------
// 2. small-M (M=4) GEMM for the time MLP: out[4,N] = act(A[4,K] @ W[N,K]^T + bias)
// ---------------------------------------------------------------------------
template<bool SILU>
__global__ void k_smallmm(const float* __restrict__ A,
                          const float* __restrict__ W,
                          const float* __restrict__ bias,
                          float* __restrict__ out, int N, int K) {
    extern __shared__ float sA[];   // 4*K floats
    for (int i = threadIdx.x; i < 4 * K; i += blockDim.x) sA[i] = A[i];
    __syncthreads();
    int w = threadIdx.x >> 5, lane = threadIdx.x & 31;
    int n = blockIdx.x * 8 + w;
    if (n >= N) return;
    const float* Wr = W + (size_t)n * K;
    float a0 = 0.f, a1 = 0.f, a2 = 0.f, a3 = 0.f;
    for (int k = lane * 4; k < K; k += 128) {
        float4 wv = *(const float4*)(Wr + k);
        float4 v0 = *(const float4*)(sA + 0 * K + k);
        float4 v1 = *(const float4*)(sA + 1 * K + k);
        float4 v2 = *(const float4*)(sA + 2 * K + k);
        float4 v3 = *(const float4*)(sA + 3 * K + k);
        a0 += wv.x * v0.x + wv.y * v0.y + wv.z * v0.z + wv.w * v0.w;
        a1 += wv.x * v1.x + wv.y * v1.y + wv.z * v1.z + wv.w * v1.w;
        a2 += wv.x * v2.x + wv.y * v2.y + wv.z * v2.z + wv.w * v2.w;
        a3 += wv.x * v3.x + wv.y * v3.y + wv.z * v3.z + wv.w * v3.w;
    }
    #pragma unroll
    for (int o = 16; o; o >>= 1) {
        a0 += __shfl_xor_sync(0xFFFFFFFFu, a0, o);
        a1 += __shfl_xor_sync(0xFFFFFFFFu, a1, o);
        a2 += __shfl_xor_sync(0xFFFFFFFFu, a2, o);
        a3 += __shfl_xor_sync(0xFFFFFFFFu, a3, o);
    }
    if (lane == 0) {
        float bb = bias[n];
        float r0 = a0 + bb, r1 = a1 + bb, r2 = a2 + bb, r3 = a3 + bb;
        if (SILU) { r0 = siluf(r0); r1 = siluf(r1); r2 = siluf(r2); r3 = siluf(r3); }
        out[0 * N + n] = r0; out[1 * N + n] = r1;
        out[2 * N + n] = r2; out[3 * N + n] = r3;
    }
}

// ---------------------------------------------------------------------------
// 3. build seq (pos + input (+temb), LayerNorm) and xn = rms_norm(seq)*rms_w
// ---------------------------------------------------------------------------
__global__ void k_build(const float* __restrict__ x_r,
                        const float* __restrict__ motion,
                        const float* __restrict__ pos,
                        const float* __restrict__ ln_g,
                        const float* __restrict__ ln_b,
                        const float* __restrict__ rms_w) {
    int r = blockIdx.x;              // 0..1567
    int b = r / LTOT, l = r % LTOT;
    float v[4];
    #pragma unroll
    for (int j = 0; j < 4; j++) {
        int i = threadIdx.x + j * 256;
        if (l < TT) {
            v[j] = pos[l * DMODEL + i] + motion[((size_t)(b * TT + l)) * DMODEL + i];
        } else {
            int lr = l - TT;
            v[j] = pos[lr * DMODEL + i] + x_r[((size_t)(b * TT + lr)) * DMODEL + i]
                 + g_embt[b * DMODEL + i];
        }
    }
    float s = v[0] + v[1] + v[2] + v[3];
    float sq = v[0]*v[0] + v[1]*v[1] + v[2]*v[2] + v[3]*v[3];
    blockReduce2(s, sq);
    float mu = s * (1.0f / DMODEL);
    float var = sq * (1.0f / DMODEL) - mu * mu;
    float rstd = rsqrtf(var + 1e-5f);
    float nrm[4];
    float s2 = 0.f;
    #pragma unroll
    for (int j = 0; j < 4; j++) {
        int i = threadIdx.x + j * 256;
        nrm[j] = (v[j] - mu) * rstd * ln_g[i] + ln_b[i];
        s2 += nrm[j] * nrm[j];
    }
    float dummy = 0.f;
    blockReduce2(s2, dummy);
    float rr = rsqrtf(s2 * (1.0f / DMODEL) + 1e-5f);
    #pragma unroll
    for (int j = 0; j < 4; j++) {
        int i = threadIdx.x + j * 256;
        g_seq[(size_t)r * DMODEL + i] = nrm[j];
        g_xn [(size_t)r * DMODEL + i] = nrm[j] * rr * rms_w[i];
    }
}

// ---------------------------------------------------------------------------
// 4. Tiled SGEMM: C[M,N] = act(A[M,K(lda)] @ W[N,K(ldw)]^T + bias)
//    ACT: 0 none, 2 softplus
// ---------------------------------------------------------------------------
template<int ACT, bool BIAS>
__global__ __launch_bounds__(256)
void sgemm_nt(const float* __restrict__ A, int lda,
              const float* __restrict__ W, int ldw,
              const float* __restrict__ bias,
              float* __restrict__ C, int ldc,
              int M, int N, int K) {
    __shared__ float As[8][128];
    __shared__ float Bs[8][128];
    int tid = threadIdx.x;
    int m0 = blockIdx.y * 128, n0 = blockIdx.x * 128;
    int lm = tid >> 1;
    int lk = (tid & 1) * 4;
    const float* Aptr = A + (size_t)(m0 + lm) * lda + lk;
    const float* Wptr = W + (size_t)(n0 + lm) * ldw + lk;
    bool aval = (m0 + lm) < M;
    bool wval = (n0 + lm) < N;
    int tx = tid & 15, ty = tid >> 4;

    float acc[8][8];
    #pragma unroll
    for (int i = 0; i < 8; i++)
        #pragma unroll
        for (int j = 0; j < 8; j++) acc[i][j] = 0.f;

    for (int k0 = 0; k0 < K; k0 += 8) {
        float4 av = aval ? *(const float4*)(Aptr + k0) : make_float4(0.f,0.f,0.f,0.f);
        float4 wv = wval ? *(const float4*)(Wptr + k0) : make_float4(0.f,0.f,0.f,0.f);
        __syncthreads();
        As[lk+0][lm] = av.x; As[lk+1][lm] = av.y; As[lk+2][lm] = av.z; As[lk+3][lm] = av.w;
        Bs[lk+0][lm] = wv.x; Bs[lk+1][lm] = wv.y; Bs[lk+2][lm] = wv.z; Bs[lk+3][lm] = wv.w;
        __syncthreads();
        #pragma unroll
        for (int k = 0; k < 8; k++) {
            float a[8], bvl[8];
            *(float4*)&a[0] = *(const float4*)&As[k][ty*8];
            *(float4*)&a[4] = *(const float4*)&As[k][ty*8+4];
            *(float4*)&bvl[0] = *(const float4*)&Bs[k][tx*8];
            *(float4*)&bvl[4] = *(const float4*)&Bs[k][tx*8+4];
            #pragma unroll
            for (int i = 0; i < 8; i++)
                #pragma unroll
                for (int j = 0; j < 8; j++)
                    acc[i][j] = fmaf(a[i], bvl[j], acc[i][j]);
        }
    }

    #pragma unroll
    for (int i = 0; i < 8; i++) {
        int m = m0 + ty * 8 + i;
        if (m >= M) continue;
        #pragma unroll
        for (int j = 0; j < 8; j++) {
            int n = n0 + tx * 8 + j;
            if (n >= N) continue;
            float v = acc[i][j];
            if (BIAS) v += bias[n];
            if (ACT == 2) v = (v > 20.f) ? v : log1pf(__expf(v));
            C[(size_t)m * ldc + n] = v;
        }
    }
}

// ---------------------------------------------------------------------------
// 5. causal depthwise conv (k=4) + bias + silu over the first DINNER cols of xz
// ---------------------------------------------------------------------------
__global__ void k_conv(const float* __restrict__ conv_w,
                       const float* __restrict__ conv_b) {
    int idx = blockIdx.x * blockDim.x + threadIdx.x;
    if (idx >= NROWS * DINNER) return;
    int c = idx % DINNER;
    int bl = idx / DINNER;
    int l = bl % LTOT;
    int b = bl / LTOT;
    float w0 = conv_w[c*4+0], w1 = conv_w[c*4+1], w2 = conv_w[c*4+2], w3 = conv_w[c*4+3];
    float acc = conv_b[c];
    const size_t rowstride = 2 * DINNER;
    size_t base = (size_t)(b * LTOT) * rowstride + c;
    if (l >= 3) acc = fmaf(w0, g_xz[base + (size_t)(l-3)*rowstride], acc);
    if (l >= 2) acc = fmaf(w1, g_xz[base + (size_t)(l-2)*rowstride], acc);
    if (l >= 1) acc = fmaf(w2, g_xz[base + (size_t)(l-1)*rowstride], acc);
    acc = fmaf(w3, g_xz[base + (size_t)l*rowstride], acc);
    g_xc[idx] = siluf(acc);
}

// ---------------------------------------------------------------------------
// 6. selective scan: 16 lanes per (b,e) channel; emit y only for l>=196,
//    already gated by silu(z) and +xc*Dp
// ---------------------------------------------------------------------------
__global__ void k_scan(const float* __restrict__ A_log,
                       const float* __restrict__ Dp) {
    int gt = blockIdx.x * blockDim.x + threadIdx.x;
    int g = gt >> 4;
    int n = threadIdx.x & 15;
    if (g >= BB * DINNER) return;
    int b = g >> 11;
    int e = g & (DINNER - 1);
    float Aen = -__expf(A_log[e * DSTATE + n]);
    float Dpe = Dp[e];
    float h = 0.f;
    for (int l = 0; l < LTOT; l++) {
        int r = b * LTOT + l;
        float d  = g_dlt[(size_t)r * DINNER + e];
        float x  = g_xc [(size_t)r * DINNER + e];
        float Bn = g_dbc[r * 96 + 64 + n];
        float Cn = g_dbc[r * 96 + 80 + n];
        float dA = __expf(d * Aen);
        h = fmaf(dA, h, d * Bn * x);
        float yv = h * Cn;
        #pragma unroll
        for (int o = 8; o; o >>= 1) yv += __shfl_xor_sync(0xFFFFFFFFu, yv, o);
        if (n == 0 && l >= TT) {
            float z = g_xz[(size_t)r * (2*DINNER) + DINNER + e];
            float yo = (yv + x * Dpe) * siluf(z);
            g_yc[(size_t)(b * TT + (l - TT)) * DINNER + e] = yo;
        }
    }
}

// ---------------------------------------------------------------------------
// 7. final: out = LayerNorm(seq[:,196:] + out_proj_result)
// ---------------------------------------------------------------------------
__global__ void k_final(const float* __restrict__ ln_g,
                        const float* __restrict__ ln_b,
                        float* __restrict__ out) {
    int r = blockIdx.x;           // 0..783
    int b = r / TT, l = r % TT;
    size_t seqrow = (size_t)(b * LTOT + TT + l) * DMODEL;
    float v[4];
    #pragma unroll
    for (int j = 0; j < 4; j++) {
        int i = threadIdx.x + j * 256;
        v[j] = g_seq[seqrow + i] + g_mo[(size_t)r * DMODEL + i];
    }
    float s = v[0] + v[1] + v[2] + v[3];
    float sq = v[0]*v[0] + v[1]*v[1] + v[2]*v[2] + v[3]*v[3];
    blockReduce2(s, sq);
    float mu = s * (1.0f / DMODEL);
    float var = sq * (1.0f / DMODEL) - mu * mu;
    float rstd = rsqrtf(var + 1e-5f);
    #pragma unroll
    for (int j = 0; j < 4; j++) {
        int i = threadIdx.x + j * 256;
        out[(size_t)r * DMODEL + i] = (v[j] - mu) * rstd * ln_g[i] + ln_b[i];
    }
}

// ---------------------------------------------------------------------------
// Launch
// ---------------------------------------------------------------------------
extern "C" void kernel_launch(void* const* d_in, const int* in_sizes, int n_in,
                              void* d_out, int out_size) {
    const float* x_r      = (const float*)d_in[0];
    const int*   ts       = (const int*)  d_in[1];
    const float* motion   = (const float*)d_in[2];
    const float* time_w1  = (const float*)d_in[3];
    const float* time_b1  = (const float*)d_in[4];
    const float* time_w2  = (const float*)d_in[5];
    const float* time_b2  = (const float*)d_in[6];
    const float* pos_emb  = (const float*)d_in[7];
    const float* ln_g     = (const float*)d_in[8];
    const float* ln_b     = (const float*)d_in[9];
    const float* in_proj  = (const float*)d_in[10];
    const float* conv_w   = (const float*)d_in[11];
    const float* conv_b   = (const float*)d_in[12];
    const float* x_proj   = (const float*)d_in[13];
    const float* dt_w     = (const float*)d_in[14];
    const float* dt_b     = (const float*)d_in[15];
    const float* A_log    = (const float*)d_in[16];
    const float* Dp       = (const float*)d_in[17];
    const float* out_proj = (const float*)d_in[18];
    const float* rms_w    = (const float*)d_in[19];
    float* out = (float*)d_out;

    float *p_temb, *p_h, *p_embt, *p_xn, *p_xz, *p_xc, *p_dbc, *p_dlt, *p_yc, *p_mo;
    cudaGetSymbolAddress((void**)&p_temb, g_temb);
    cudaGetSymbolAddress((void**)&p_h,    g_h);
    cudaGetSymbolAddress((void**)&p_embt, g_embt);
    cudaGetSymbolAddress((void**)&p_xn,   g_xn);
    cudaGetSymbolAddress((void**)&p_xz,   g_xz);
    cudaGetSymbolAddress((void**)&p_xc,   g_xc);
    cudaGetSymbolAddress((void**)&p_dbc,  g_dbc);
    cudaGetSymbolAddress((void**)&p_dlt,  g_dlt);
    cudaGetSymbolAddress((void**)&p_yc,   g_yc);
    cudaGetSymbolAddress((void**)&p_mo,   g_mo);

    // 1. time embedding
    k_temb<<<BB, 512>>>(ts);

    // 2. time MLP
    k_smallmm<true ><<<2048/8, 256, 4*1024*sizeof(float)>>>(p_temb, time_w1, time_b1, p_h, 2048, 1024);
    k_smallmm<false><<<1024/8, 256, 4*2048*sizeof(float)>>>(p_h,    time_w2, time_b2, p_embt, 1024, 2048);

    // 3. build seq (LN) + rms-norm
    k_build<<<NROWS, 256>>>(x_r, motion, pos_emb, ln_g, ln_b, rms_w);

    // 4. in_proj: xz[1568,4096] = xn @ in_proj^T
    {
        dim3 grid(4096/128, (NROWS + 127)/128);
        sgemm_nt<0,false><<<grid, 256>>>(p_xn, DMODEL, in_proj, DMODEL, nullptr,
                                         p_xz, 2*DINNER, NROWS, 2*DINNER, DMODEL);
    }

    // 5. conv + silu
    k_conv<<<(NROWS*DINNER + 255)/256, 256>>>(conv_w, conv_b);

    // 6. x_proj: dbc[1568,96] = xc @ x_proj^T
    {
        dim3 grid(1, (NROWS + 127)/128);
        sgemm_nt<0,false><<<grid, 256>>>(p_xc, DINNER, x_proj, DINNER, nullptr,
                                         p_dbc, 96, NROWS, 96, DINNER);
    }

    // 7. dt_proj: delta[1568,2048] = softplus(dbc[:, :64] @ dt_w^T + dt_b)
    {
        dim3 grid(2048/128, (NROWS + 127)/128);
        sgemm_nt<2,true><<<grid, 256>>>(p_dbc, 96, dt_w, DTRANK, dt_b,
                                        p_dlt, DINNER, NROWS, DINNER, DTRANK);
    }

    // 8. selective scan (emits gated y only for l>=196, compact)
    k_scan<<<(BB*DINNER*16 + 255)/256, 256>>>(A_log, Dp);

    // 9. out_proj on surviving rows only: mo[784,1024] = yc @ out_proj^T
    {
        dim3 grid(1024/128, (NOUT + 127)/128);
        sgemm_nt<0,false><<<grid, 256>>>(p_yc, DINNER, out_proj, DINNER, nullptr,
                                         p_mo, DMODEL, NOUT, DMODEL, DINNER);
    }

    // 10. residual + final LN -> d_out
    k_final<<<NOUT, 256>>>(ln_g, ln_b, out);
}

// round 2
// speedup vs baseline: 2.2521x; 2.2521x over previous
#include <cuda_runtime.h>
#include <cuda_bf16.h>
#include <math.h>
#include <stdint.h>

// ---------------------------------------------------------------------------
// Problem constants
// ---------------------------------------------------------------------------
#define BB 4
#define TT 196
#define LTOT 392            // TM + T
#define DMODEL 1024
#define DINNER 2048
#define DSTATE 16
#define DCONV 4
#define DTRANK 64
#define NROWS (BB*LTOT)     // 1568
#define NOUT  (BB*TT)       // 784

// ---------------------------------------------------------------------------
// Device scratch (static: no allocations allowed)
// ---------------------------------------------------------------------------
__device__ float g_temb[BB * 1024];
__device__ float g_h   [BB * 2048];
__device__ float g_embt[BB * 1024];
__device__ float g_seq [NROWS * DMODEL];     // LN'ed concat sequence
__device__ float g_xz  [NROWS * (2*DINNER)]; // in_proj out
__device__ float g_xc  [NROWS * DINNER];     // silu(conv(x))
__device__ float g_dbc [NROWS * 96];         // x_proj out (dt|B|C)
__device__ float g_dlt [NROWS * DINNER];     // softplus(dt_proj)
__device__ float g_yc  [NOUT * DINNER];      // scan out (l>=196, compact)
__device__ float g_mo  [NOUT * DMODEL];      // out_proj result

// bf16 split operand buffers (K' = 3K): A-mode = [hi|lo|hi], W-mode = [hi|hi|lo]
__device__ __nv_bfloat16 g_xnb [NROWS * 3*DMODEL];   // rms_norm(seq), A-mode
__device__ __nv_bfloat16 g_ipb [4096  * 3*DMODEL];   // in_proj_w, W-mode
__device__ __nv_bfloat16 g_xcb [NROWS * 3*DINNER];   // xc, A-mode
__device__ __nv_bfloat16 g_xpb [96    * 3*DINNER];   // x_proj_w, W-mode
__device__ __nv_bfloat16 g_dtb [NROWS * 3*DTRANK];   // dbc[:, :64], A-mode
__device__ __nv_bfloat16 g_dtwb[DINNER* 3*DTRANK];   // dt_proj_w, W-mode
__device__ __nv_bfloat16 g_ycb [NOUT  * 3*DINNER];   // yc, A-mode
__device__ __nv_bfloat16 g_opb [DMODEL* 3*DINNER];   // out_proj_w, W-mode

// ---------------------------------------------------------------------------
// Helpers
// ---------------------------------------------------------------------------
__device__ __forceinline__ float siluf(float x) {
    return x / (1.0f + __expf(-x));
}

__device__ __forceinline__ void bsplit(float x, __nv_bfloat16& hi, __nv_bfloat16& lo) {
    hi = __float2bfloat16(x);
    lo = __float2bfloat16(x - __bfloat162float(hi));
}

__device__ __forceinline__ void blockReduce2(float& a, float& b) {
    __shared__ float s[66];
    #pragma unroll
    for (int o = 16; o; o >>= 1) {
        a += __shfl_xor_sync(0xFFFFFFFFu, a, o);
        b += __shfl_xor_sync(0xFFFFFFFFu, b, o);
    }
    int w = threadIdx.x >> 5, lane = threadIdx.x & 31;
    if (lane == 0) { s[w] = a; s[32 + w] = b; }
    __syncthreads();
    if (threadIdx.x == 0) {
        float sa = 0.f, sb = 0.f;
        int nw = blockDim.x >> 5;
        for (int i = 0; i < nw; i++) { sa += s[i]; sb += s[32 + i]; }
        s[64] = sa; s[65] = sb;
    }
    __syncthreads();
    a = s[64]; b = s[65];
    __syncthreads();
}

// ---------------------------------------------------------------------------
// bf16 split conversion kernels
// ---------------------------------------------------------------------------
// W-mode: dst[n, :] = [hi | hi | lo] over K' = 3K
__global__ void k_wsplit(const float* __restrict__ src, __nv_bfloat16* __restrict__ dst,
                         int N, int K) {
    int idx = blockIdx.x * blockDim.x + threadIdx.x;
    if (idx >= N * K) return;
    int n = idx / K, k = idx - n * K;
    __nv_bfloat16 hi, lo;
    bsplit(src[idx], hi, lo);
    __nv_bfloat16* d = dst + (size_t)n * (3 * K);
    d[k] = hi; d[K + k] = hi; d[2 * K + k] = lo;
}

// A-mode: dst[r, :] = [hi | lo | hi], src has row stride lds
__global__ void k_asplit(const float* __restrict__ src, int lds,
                         __nv_bfloat16* __restrict__ dst, int R, int K) {
    int idx = blockIdx.x * blockDim.x + threadIdx.x;
    if (idx >= R * K) return;
    int r = idx / K, k = idx - r * K;
    __nv_bfloat16 hi, lo;
    bsplit(src[(size_t)r * lds + k], hi, lo);
    __nv_bfloat16* d = dst + (size_t)r * (3 * K);
    d[k] = hi; d[K + k] = lo; d[2 * K + k] = hi;
}

// ---------------------------------------------------------------------------
// 1. timestep embedding
// ---------------------------------------------------------------------------
__global__ void k_temb(const int* __restrict__ ts) {
    int b = blockIdx.x;
    int i = threadIdx.x;                // 0..511
    float t = (float)ts[b];
    float freq = __expf(-9.210340371976184f * (float)i / 512.0f);
    float arg = t * freq;
    g_temb[b * 1024 + i]       = cosf(arg);
    g_temb[b * 1024 + 512 + i] = sinf(arg);
}

// ---------------------------------------------------------------------------
// 2. small-M (M=4) GEMM for the time MLP
// ---------------------------------------------------------------------------
template<bool SILU>
__global__ void k_smallmm(const float* __restrict__ A,
                          const float* __restrict__ W,
                          const float* __restrict__ bias,
                          float* __restrict__ out, int N, int K) {
    extern __shared__ float sA[];   // 4*K floats
    for (int i = threadIdx.x; i < 4 * K; i += blockDim.x) sA[i] = A[i];
    __syncthreads();
    int w = threadIdx.x >> 5, lane = threadIdx.x & 31;
    int n = blockIdx.x * 8 + w;
    if (n >= N) return;
    const float* Wr = W + (size_t)n * K;
    float a0 = 0.f, a1 = 0.f, a2 = 0.f, a3 = 0.f;
    for (int k = lane * 4; k < K; k += 128) {
        float4 wv = *(const float4*)(Wr + k);
        float4 v0 = *(const float4*)(sA + 0 * K + k);
        float4 v1 = *(const float4*)(sA + 1 * K + k);
        float4 v2 = *(const float4*)(sA + 2 * K + k);
        float4 v3 = *(const float4*)(sA + 3 * K + k);
        a0 += wv.x * v0.x + wv.y * v0.y + wv.z * v0.z + wv.w * v0.w;
        a1 += wv.x * v1.x + wv.y * v1.y + wv.z * v1.z + wv.w * v1.w;
        a2 += wv.x * v2.x + wv.y * v2.y + wv.z * v2.z + wv.w * v2.w;
        a3 += wv.x * v3.x + wv.y * v3.y + wv.z * v3.z + wv.w * v3.w;
    }
    #pragma unroll
    for (int o = 16; o; o >>= 1) {
        a0 += __shfl_xor_sync(0xFFFFFFFFu, a0, o);
        a1 += __shfl_xor_sync(0xFFFFFFFFu, a1, o);
        a2 += __shfl_xor_sync(0xFFFFFFFFu, a2, o);
        a3 += __shfl_xor_sync(0xFFFFFFFFu, a3, o);
    }
    if (lane == 0) {
        float bb = bias[n];
        float r0 = a0 + bb, r1 = a1 + bb, r2 = a2 + bb, r3 = a3 + bb;
        if (SILU) { r0 = siluf(r0); r1 = siluf(r1); r2 = siluf(r2); r3 = siluf(r3); }
        out[0 * N + n] = r0; out[1 * N + n] = r1;
        out[2 * N + n] = r2; out[3 * N + n] = r3;
    }
}

// ---------------------------------------------------------------------------
// 3. build seq (pos + input (+temb), LayerNorm), write rms_norm split to g_xnb
// ---------------------------------------------------------------------------
__global__ void k_build(const float* __restrict__ x_r,
                        const float* __restrict__ motion,
                        const float* __restrict__ pos,
                        const float* __restrict__ ln_g,
                        const float* __restrict__ ln_b,
                        const float* __restrict__ rms_w) {
    int r = blockIdx.x;              // 0..1567
    int b = r / LTOT, l = r % LTOT;
    float v[4];
    #pragma unroll
    for (int j = 0; j < 4; j++) {
        int i = threadIdx.x + j * 256;
        if (l < TT) {
            v[j] = pos[l * DMODEL + i] + motion[((size_t)(b * TT + l)) * DMODEL + i];
        } else {
            int lr = l - TT;
            v[j] = pos[lr * DMODEL + i] + x_r[((size_t)(b * TT + lr)) * DMODEL + i]
                 + g_embt[b * DMODEL + i];
        }
    }
    float s = v[0] + v[1] + v[2] + v[3];
    float sq = v[0]*v[0] + v[1]*v[1] + v[2]*v[2] + v[3]*v[3];
    blockReduce2(s, sq);
    float mu = s * (1.0f / DMODEL);
    float var = sq * (1.0f / DMODEL) - mu * mu;
    float rstd = rsqrtf(var + 1e-5f);
    float nrm[4];
    float s2 = 0.f;
    #pragma unroll
    for (int j = 0; j < 4; j++) {
        int i = threadIdx.x + j * 256;
        nrm[j] = (v[j] - mu) * rstd * ln_g[i] + ln_b[i];
        s2 += nrm[j] * nrm[j];
    }
    float dummy = 0.f;
    blockReduce2(s2, dummy);
    float rr = rsqrtf(s2 * (1.0f / DMODEL) + 1e-5f);
    __nv_bfloat16* xb = g_xnb + (size_t)r * (3 * DMODEL);
    #pragma unroll
    for (int j = 0; j < 4; j++) {
        int i = threadIdx.x + j * 256;
        g_seq[(size_t)r * DMODEL + i] = nrm[j];
        float xn = nrm[j] * rr * rms_w[i];
        __nv_bfloat16 hi, lo;
        bsplit(xn, hi, lo);
        xb[i] = hi; xb[DMODEL + i] = lo; xb[2 * DMODEL + i] = hi;
    }
}

// ---------------------------------------------------------------------------
// 4. bf16 tensor-core GEMM: C[M,N] = act(A'[M,K'] @ W'[N,K']^T (+bias))
//    128x128 block tile, 8 warps (2x4) of 64x32, BK=32, 3-stage cp.async.
//    ACT: 0 none, 2 softplus
// ---------------------------------------------------------------------------
#define GSTAGES 3
#define GSMEM_BYTES (GSTAGES * 16384)

__device__ __forceinline__ void cpa16(uint32_t d, const void* g, bool v) {
    int sz = v ? 16 : 0;
    asm volatile("cp.async.cg.shared.global [%0], [%1], 16, %2;\n"
                 :: "r"(d), "l"(g), "r"(sz));
}
__device__ __forceinline__ void ldm4(uint32_t a, uint32_t& r0, uint32_t& r1,
                                     uint32_t& r2, uint32_t& r3) {
    asm volatile("ldmatrix.sync.aligned.m8n8.x4.shared.b16 {%0,%1,%2,%3}, [%4];"
                 : "=r"(r0), "=r"(r1), "=r"(r2), "=r"(r3) : "r"(a));
}
__device__ __forceinline__ void mma16816(float* c, const uint32_t* a, const uint32_t* b) {
    asm volatile(
        "mma.sync.aligned.m16n8k16.row.col.f32.bf16.bf16.f32 "
        "{%0,%1,%2,%3},{%4,%5,%6,%7},{%8,%9},{%0,%1,%2,%3};"
        : "+f"(c[0]), "+f"(c[1]), "+f"(c[2]), "+f"(c[3])
        : "r"(a[0]), "r"(a[1]), "r"(a[2]), "r"(a[3]), "r"(b[0]), "r"(b[1]));
}

template<int ACT, bool BIAS>
__global__ void __launch_bounds__(256)
gemm_bf16(const __nv_bfloat16* __restrict__ A, const __nv_bfloat16* __restrict__ Bw,
          const float* __restrict__ bias, float* __restrict__ C,
          int M, int N, int K, int ldc) {
    extern __shared__ __nv_bfloat16 smem[];
    uint32_t sbase = (uint32_t)__cvta_generic_to_shared(smem);
    const int tid = threadIdx.x;
    const int wid = tid >> 5, lane = tid & 31;
    const int wm = wid >> 2, wn = wid & 3;         // 2 x 4 warp grid
    const int m0 = blockIdx.y * 128, n0 = blockIdx.x * 128;
    const int iters = K >> 5;

    float acc[4][4][4];
    #pragma unroll
    for (int i = 0; i < 4; i++)
        #pragma unroll
        for (int j = 0; j < 4; j++)
            #pragma unroll
            for (int q = 0; q < 4; q++) acc[i][j][q] = 0.f;

    // swizzled 16B-chunk offset (in 16B units): row r (0..127), chunk c (0..3)
    auto sw = [](int r, int c) { return r * 4 + (c ^ ((r >> 1) & 3)); };

    auto load_stage = [&](int s, int k0) {
        uint32_t sa = sbase + s * 16384;
        uint32_t sb = sa + 8192;
        #pragma unroll
        for (int hh = 0; hh < 2; hh++) {
            int cid = tid + hh * 256;          // 0..511
            int r = cid >> 2, c = cid & 3;
            int m = m0 + r; bool va = m < M;
            cpa16(sa + sw(r, c) * 16,
                  A + (size_t)(va ? m : 0) * K + k0 + c * 8, va);
            int n = n0 + r; bool vb = n < N;
            cpa16(sb + sw(r, c) * 16,
                  Bw + (size_t)(vb ? n : 0) * K + k0 + c * 8, vb);
        }
    };

    // prefetch 2 stages
    load_stage(0, 0);
    asm volatile("cp.async.commit_group;\n" ::: "memory");
    load_stage(1, 32);
    asm volatile("cp.async.commit_group;\n" ::: "memory");

    for (int it = 0; it < iters; it++) {
        asm volatile("cp.async.wait_group %0;\n" :: "n"(1) : "memory");
        __syncthreads();
        if (it + 2 < iters) load_stage((it + 2) % GSTAGES, (it + 2) * 32);
        asm volatile("cp.async.commit_group;\n" ::: "memory");

        int s = it % GSTAGES;
        uint32_t sa = sbase + s * 16384;
        uint32_t sb = sa + 8192;
        #pragma unroll
        for (int h = 0; h < 2; h++) {
            uint32_t ra[4][4];
            #pragma unroll
            for (int i = 0; i < 4; i++) {
                int r = wm * 64 + i * 16 + (lane & 15);
                int c = 2 * h + (lane >> 4);
                ldm4(sa + sw(r, c) * 16, ra[i][0], ra[i][1], ra[i][2], ra[i][3]);
            }
            uint32_t rb[4][2];
            #pragma unroll
            for (int jj = 0; jj < 2; jj++) {
                int t = jj * 2 + (lane >> 4);          // n-tile within warp
                int nr = wn * 32 + t * 8 + (lane & 7);
                int c = 2 * h + ((lane >> 3) & 1);
                uint32_t q0, q1, q2, q3;
                ldm4(sb + sw(nr, c) * 16, q0, q1, q2, q3);
                rb[jj*2][0] = q0; rb[jj*2][1] = q1;
                rb[jj*2+1][0] = q2; rb[jj*2+1][1] = q3;
            }
            #pragma unroll
            for (int i = 0; i < 4; i++)
                #pragma unroll
                for (int j = 0; j < 4; j++)
                    mma16816(acc[i][j], ra[i], rb[j]);
        }
    }
    asm volatile("cp.async.wait_group %0;\n" :: "n"(0) : "memory");

    // epilogue
    #pragma unroll
    for (int i = 0; i < 4; i++) {
        int rbase = m0 + wm * 64 + i * 16 + (lane >> 2);
        #pragma unroll
        for (int j = 0; j < 4; j++) {
            int col = n0 + wn * 32 + j * 8 + 2 * (lane & 3);
            if (col >= N) continue;
            float b0 = 0.f, b1 = 0.f;
            if (BIAS) { b0 = bias[col]; b1 = bias[col + 1]; }
            #pragma unroll
            for (int half = 0; half < 2; half++) {
                int m = rbase + half * 8;
                if (m >= M) continue;
                float v0 = acc[i][j][half * 2 + 0] + b0;
                float v1 = acc[i][j][half * 2 + 1] + b1;
                if (ACT == 2) {
                    v0 = (v0 > 20.f) ? v0 : log1pf(__expf(v0));
                    v1 = (v1 > 20.f) ? v1 : log1pf(__expf(v1));
                }
                *(float2*)&C[(size_t)m * ldc + col] = make_float2(v0, v1);
            }
        }
    }
}

// ---------------------------------------------------------------------------
// 5. causal depthwise conv (k=4) + bias + silu, write fp32 + bf16 split
// ---------------------------------------------------------------------------
__global__ void k_conv(const float* __restrict__ conv_w,
                       const float* __restrict__ conv_b) {
    int idx = blockIdx.x * blockDim.x + threadIdx.x;
    if (idx >= NROWS * DINNER) return;
    int c = idx % DINNER;
    int bl = idx / DINNER;
    int l = bl % LTOT;
    int b = bl / LTOT;
    float w0 = conv_w[c*4+0], w1 = conv_w[c*4+1], w2 = conv_w[c*4+2], w3 = conv_w[c*4+3];
    float acc = conv_b[c];
    const size_t rowstride = 2 * DINNER;
    size_t base = (size_t)(b * LTOT) * rowstride + c;
    if (l >= 3) acc = fmaf(w0, g_xz[base + (size_t)(l-3)*rowstride], acc);
    if (l >= 2) acc = fmaf(w1, g_xz[base + (size_t)(l-2)*rowstride], acc);
    if (l >= 1) acc = fmaf(w2, g_xz[base + (size_t)(l-1)*rowstride], acc);
    acc = fmaf(w3, g_xz[base + (size_t)l*rowstride], acc);
    float xv = siluf(acc);
    g_xc[idx] = xv;
    __nv_bfloat16 hi, lo;
    bsplit(xv, hi, lo);
    __nv_bfloat16* d = g_xcb + (size_t)bl * (3 * DINNER);
    d[c] = hi; d[DINNER + c] = lo; d[2 * DINNER + c] = hi;
}

// ---------------------------------------------------------------------------
// 6. selective scan
// ---------------------------------------------------------------------------
__global__ void k_scan(const float* __restrict__ A_log,
                       const float* __restrict__ Dp) {
    int gt = blockIdx.x * blockDim.x + threadIdx.x;
    int g = gt >> 4;
    int n = threadIdx.x & 15;
    if (g >= BB * DINNER) return;
    int b = g >> 11;
    int e = g & (DINNER - 1);
    float Aen = -__expf(A_log[e * DSTATE + n]);
    float Dpe = Dp[e];
    float h = 0.f;
    for (int l = 0; l < LTOT; l++) {
        int r = b * LTOT + l;
        float d  = g_dlt[(size_t)r * DINNER + e];
        float x  = g_xc [(size_t)r * DINNER + e];
        float Bn = g_dbc[r * 96 + 64 + n];
        float Cn = g_dbc[r * 96 + 80 + n];
        float dA = __expf(d * Aen);
        h = fmaf(dA, h, d * Bn * x);
        float yv = h * Cn;
        #pragma unroll
        for (int o = 8; o; o >>= 1) yv += __shfl_xor_sync(0xFFFFFFFFu, yv, o);
        if (n == 0 && l >= TT) {
            float z = g_xz[(size_t)r * (2*DINNER) + DINNER + e];
            float yo = (yv + x * Dpe) * siluf(z);
            g_yc[(size_t)(b * TT + (l - TT)) * DINNER + e] = yo;
        }
    }
}

// ---------------------------------------------------------------------------
// 7. final: out = LayerNorm(seq[:,196:] + out_proj_result)
// ---------------------------------------------------------------------------
__global__ void k_final(const float* __restrict__ ln_g,
                        const float* __restrict__ ln_b,
                        float* __restrict__ out) {
    int r = blockIdx.x;           // 0..783
    int b = r / TT, l = r % TT;
    size_t seqrow = (size_t)(b * LTOT + TT + l) * DMODEL;
    float v[4];
    #pragma unroll
    for (int j = 0; j < 4; j++) {
        int i = threadIdx.x + j * 256;
        v[j] = g_seq[seqrow + i] + g_mo[(size_t)r * DMODEL + i];
    }
    float s = v[0] + v[1] + v[2] + v[3];
    float sq = v[0]*v[0] + v[1]*v[1] + v[2]*v[2] + v[3]*v[3];
    blockReduce2(s, sq);
    float mu = s * (1.0f / DMODEL);
    float var = sq * (1.0f / DMODEL) - mu * mu;
    float rstd = rsqrtf(var + 1e-5f);
    #pragma unroll
    for (int j = 0; j < 4; j++) {
        int i = threadIdx.x + j * 256;
        out[(size_t)r * DMODEL + i] = (v[j] - mu) * rstd * ln_g[i] + ln_b[i];
    }
}

// ---------------------------------------------------------------------------
// Launch
// ---------------------------------------------------------------------------
extern "C" void kernel_launch(void* const* d_in, const int* in_sizes, int n_in,
                              void* d_out, int out_size) {
    const float* x_r      = (const float*)d_in[0];
    const int*   ts       = (const int*)  d_in[1];
    const float* motion   = (const float*)d_in[2];
    const float* time_w1  = (const float*)d_in[3];
    const float* time_b1  = (const float*)d_in[4];
    const float* time_w2  = (const float*)d_in[5];
    const float* time_b2  = (const float*)d_in[6];
    const float* pos_emb  = (const float*)d_in[7];
    const float* ln_g     = (const float*)d_in[8];
    const float* ln_b     = (const float*)d_in[9];
    const float* in_proj  = (const float*)d_in[10];
    const float* conv_w   = (const float*)d_in[11];
    const float* conv_b   = (const float*)d_in[12];
    const float* x_proj   = (const float*)d_in[13];
    const float* dt_w     = (const float*)d_in[14];
    const float* dt_b     = (const float*)d_in[15];
    const float* A_log    = (const float*)d_in[16];
    const float* Dp       = (const float*)d_in[17];
    const float* out_proj = (const float*)d_in[18];
    const float* rms_w    = (const float*)d_in[19];
    float* out = (float*)d_out;

    float *p_temb, *p_h, *p_embt, *p_xz, *p_dbc, *p_dlt, *p_yc, *p_mo;
    __nv_bfloat16 *p_xnb, *p_ipb, *p_xcb, *p_xpb, *p_dtb, *p_dtwb, *p_ycb, *p_opb;
    cudaGetSymbolAddress((void**)&p_temb, g_temb);
    cudaGetSymbolAddress((void**)&p_h,    g_h);
    cudaGetSymbolAddress((void**)&p_embt, g_embt);
    cudaGetSymbolAddress((void**)&p_xz,   g_xz);
    cudaGetSymbolAddress((void**)&p_dbc,  g_dbc);
    cudaGetSymbolAddress((void**)&p_dlt,  g_dlt);
    cudaGetSymbolAddress((void**)&p_yc,   g_yc);
    cudaGetSymbolAddress((void**)&p_mo,   g_mo);
    cudaGetSymbolAddress((void**)&p_xnb,  g_xnb);
    cudaGetSymbolAddress((void**)&p_ipb,  g_ipb);
    cudaGetSymbolAddress((void**)&p_xcb,  g_xcb);
    cudaGetSymbolAddress((void**)&p_xpb,  g_xpb);
    cudaGetSymbolAddress((void**)&p_dtb,  g_dtb);
    cudaGetSymbolAddress((void**)&p_dtwb, g_dtwb);
    cudaGetSymbolAddress((void**)&p_ycb,  g_ycb);
    cudaGetSymbolAddress((void**)&p_opb,  g_opb);

    // weight splits (independent of data path)
    k_wsplit<<<(4096*1024 + 255)/256, 256>>>(in_proj,  p_ipb, 4096, 1024);
    k_wsplit<<<(96*2048   + 255)/256, 256>>>(x_proj,   p_xpb, 96,   2048);
    k_wsplit<<<(2048*64   + 255)/256, 256>>>(dt_w,     p_dtwb, 2048, 64);
    k_wsplit<<<(1024*2048 + 255)/256, 256>>>(out_proj, p_opb, 1024, 2048);

    // 1-2. time embedding + MLP
    k_temb<<<BB, 512>>>(ts);
    k_smallmm<true ><<<2048/8, 256, 4*1024*sizeof(float)>>>(p_temb, time_w1, time_b1, p_h, 2048, 1024);
    k_smallmm<false><<<1024/8, 256, 4*2048*sizeof(float)>>>(p_h,    time_w2, time_b2, p_embt, 1024, 2048);

    // 3. build seq (LN) + rms-norm split
    k_build<<<NROWS, 256>>>(x_r, motion, pos_emb, ln_g, ln_b, rms_w);

    // 4. in_proj: xz[1568,4096] = xnb @ ipb^T   (K' = 3072)
    {
        dim3 grid(4096/128, (NROWS + 127)/128);
        gemm_bf16<0,false><<<grid, 256, GSMEM_BYTES>>>(p_xnb, p_ipb, nullptr,
                                                       p_xz, NROWS, 4096, 3*DMODEL, 4096);
    }

    // 5. conv + silu + split
    k_conv<<<(NROWS*DINNER + 255)/256, 256>>>(conv_w, conv_b);

    // 6. x_proj: dbc[1568,96] = xcb @ xpb^T   (K' = 6144)
    {
        dim3 grid(1, (NROWS + 127)/128);
        gemm_bf16<0,false><<<grid, 256, GSMEM_BYTES>>>(p_xcb, p_xpb, nullptr,
                                                       p_dbc, NROWS, 96, 3*DINNER, 96);
    }

    // 7. dt input split + dt_proj: dlt = softplus(dtb @ dtwb^T + dt_b)  (K' = 192)
    k_asplit<<<(NROWS*64 + 255)/256, 256>>>(p_dbc, 96, p_dtb, NROWS, 64);
    {
        dim3 grid(2048/128, (NROWS + 127)/128);
        gemm_bf16<2,true><<<grid, 256, GSMEM_BYTES>>>(p_dtb, p_dtwb, dt_b,
                                                      p_dlt, NROWS, 2048, 3*DTRANK, DINNER);
    }

    // 8. selective scan
    k_scan<<<(BB*DINNER*16 + 255)/256, 256>>>(A_log, Dp);

    // 9. yc split + out_proj: mo[784,1024] = ycb @ opb^T  (K' = 6144)
    k_asplit<<<(NOUT*DINNER + 255)/256, 256>>>(p_yc, DINNER, p_ycb, NOUT, DINNER);
    {
        dim3 grid(1024/128, (NOUT + 127)/128);
        gemm_bf16<0,false><<<grid, 256, GSMEM_BYTES>>>(p_ycb, p_opb, nullptr,
                                                       p_mo, NOUT, 1024, 3*DINNER, DMODEL);
    }

    // 10. residual + final LN -> d_out
    k_final<<<NOUT, 256>>>(ln_g, ln_b, out);
}

// round 9
// speedup vs baseline: 2.6987x; 1.1983x over previous
#include <cuda_runtime.h>
#include <cuda_bf16.h>
#include <math.h>
#include <stdint.h>

// ---------------------------------------------------------------------------
// Problem constants
// ---------------------------------------------------------------------------
#define BB 4
#define TT 196
#define LTOT 392            // TM + T
#define DMODEL 1024
#define DINNER 2048
#define DSTATE 16
#define DCONV 4
#define DTRANK 64
#define NROWS (BB*LTOT)     // 1568
#define NOUT  (BB*TT)       // 784
#define KSPLIT 4

// ---------------------------------------------------------------------------
// Device scratch (static: no allocations allowed)
// ---------------------------------------------------------------------------
__device__ float g_temb[BB * 1024];
__device__ float g_h   [BB * 2048];
__device__ float g_embt[BB * 1024];
__device__ float g_seq [NROWS * DMODEL];     // LN'ed concat sequence
__device__ float g_x   [NROWS * DINNER];     // in_proj x-half (pre conv)
__device__ float g_z   [NOUT  * DINNER];     // in_proj z-half, l>=196 compact
__device__ float g_xc  [NROWS * DINNER];     // silu(conv(x))
__device__ float g_dbcp[KSPLIT * NROWS * 96];// x_proj split-K partials
__device__ float g_dbc [NROWS * 96];         // x_proj out (dt|B|C)
__device__ float g_dlt [NROWS * DINNER];     // softplus(dt_proj)
__device__ float g_mo  [NOUT * DMODEL];      // out_proj result

// bf16 split operand buffers (K' = 3K): A-mode = [hi|lo|hi], W-mode = [hi|hi|lo]
__device__ __nv_bfloat16 g_xnb [NROWS * 3*DMODEL];   // rms_norm(seq), A-mode
__device__ __nv_bfloat16 g_ipb [4096  * 3*DMODEL];   // in_proj_w, W-mode
__device__ __nv_bfloat16 g_xcb [NROWS * 3*DINNER];   // xc, A-mode
__device__ __nv_bfloat16 g_xpb [96    * 3*DINNER];   // x_proj_w, W-mode
__device__ __nv_bfloat16 g_dtb [NROWS * 3*DTRANK];   // dbc[:, :64], A-mode
__device__ __nv_bfloat16 g_dtwb[DINNER* 3*DTRANK];   // dt_proj_w, W-mode
__device__ __nv_bfloat16 g_ycb [NOUT  * 3*DINNER];   // scan out, A-mode
__device__ __nv_bfloat16 g_opb [DMODEL* 3*DINNER];   // out_proj_w, W-mode

// ---------------------------------------------------------------------------
// Helpers
// ---------------------------------------------------------------------------
__device__ __forceinline__ float siluf(float x) {
    return x / (1.0f + __expf(-x));
}

__device__ __forceinline__ void bsplit(float x, __nv_bfloat16& hi, __nv_bfloat16& lo) {
    hi = __float2bfloat16(x);
    lo = __float2bfloat16(x - __bfloat162float(hi));
}

__device__ __forceinline__ void blockReduce2(float& a, float& b) {
    __shared__ float s[66];
    #pragma unroll
    for (int o = 16; o; o >>= 1) {
        a += __shfl_xor_sync(0xFFFFFFFFu, a, o);
        b += __shfl_xor_sync(0xFFFFFFFFu, b, o);
    }
    int w = threadIdx.x >> 5, lane = threadIdx.x & 31;
    if (lane == 0) { s[w] = a; s[32 + w] = b; }
    __syncthreads();
    if (threadIdx.x == 0) {
        float sa = 0.f, sb = 0.f;
        int nw = blockDim.x >> 5;
        for (int i = 0; i < nw; i++) { sa += s[i]; sb += s[32 + i]; }
        s[64] = sa; s[65] = sb;
    }
    __syncthreads();
    a = s[64]; b = s[65];
    __syncthreads();
}

// ---------------------------------------------------------------------------
// mma.sync building blocks
// ---------------------------------------------------------------------------
__device__ __forceinline__ void cpa16(uint32_t d, const void* g, bool v) {
    int sz = v ? 16 : 0;
    asm volatile("cp.async.cg.shared.global [%0], [%1], 16, %2;\n"
                 :: "r"(d), "l"(g), "r"(sz));
}
__device__ __forceinline__ void ldm4(uint32_t a, uint32_t& r0, uint32_t& r1,
                                     uint32_t& r2, uint32_t& r3) {
    asm volatile("ldmatrix.sync.aligned.m8n8.x4.shared.b16 {%0,%1,%2,%3}, [%4];"
                 : "=r"(r0), "=r"(r1), "=r"(r2), "=r"(r3) : "r"(a));
}
__device__ __forceinline__ void mma16816(float* c, const uint32_t* a, const uint32_t* b) {
    asm volatile(
        "mma.sync.aligned.m16n8k16.row.col.f32.bf16.bf16.f32 "
        "{%0,%1,%2,%3},{%4,%5,%6,%7},{%8,%9},{%0,%1,%2,%3};"
        : "+f"(c[0]), "+f"(c[1]), "+f"(c[2]), "+f"(c[3])
        : "r"(a[0]), "r"(a[1]), "r"(a[2]), "r"(a[3]), "r"(b[0]), "r"(b[1]));
}

// ---------------------------------------------------------------------------
// bf16 tensor-core GEMM: C[M,N] = act(A[M,K(lda)] @ W[N,K(ldw)]^T (+bias))
//   128x128 CTA tile, 8 warps (2x4) of 64x32, BK=64, 3-stage cp.async.
//   K must be a multiple of 64. gridDim.z = split-K count: slice z handles
//   K columns [z*K, (z+1)*K) of A/W (koff = z*K) and writes C + z*M*ldc.
//   AMAP: A row m reads source row (m/196)*392 + 196 + m%196.
//   ACT: 0 none, 2 softplus
// ---------------------------------------------------------------------------
#define GST 3
#define GSMEM_BYTES (GST * 32768)

template<int ACT, bool BIAS, bool AMAP>
__global__ void __launch_bounds__(256, 2)
gemm_bf16(const __nv_bfloat16* __restrict__ A, int lda,
          const __nv_bfloat16* __restrict__ Bw, int ldw,
          const float* __restrict__ bias, float* __restrict__ C, int ldc,
          int M, int N, int K) {
    extern __shared__ __nv_bfloat16 smem[];
    uint32_t sbase = (uint32_t)__cvta_generic_to_shared(smem);
    const int tid = threadIdx.x;
    const int wid = tid >> 5, lane = tid & 31;
    const int wm = wid >> 2, wn = wid & 3;         // 2 x 4 warp grid
    const int m0 = blockIdx.y * 128, n0 = blockIdx.x * 128;
    const int koff = blockIdx.z * K;
    C += (size_t)blockIdx.z * M * ldc;
    const int iters = K >> 6;

    float acc[4][4][4];
    #pragma unroll
    for (int i = 0; i < 4; i++)
        #pragma unroll
        for (int j = 0; j < 4; j++)
            #pragma unroll
            for (int q = 0; q < 4; q++) acc[i][j][q] = 0.f;

    auto load_stage = [&](int t) {
        int s = t % GST;
        uint32_t sa = sbase + s * 32768;
        uint32_t sb = sa + 16384;
        #pragma unroll
        for (int q = 0; q < 4; q++) {
            int cid = tid + q * 256;           // 0..1023
            int r = cid >> 3, c = cid & 7;
            int cs = c ^ (r & 7);
            int gcol = koff + t * 64 + c * 8;
            int m = m0 + r; bool va = m < M;
            int msrc = 0;
            if (va) msrc = AMAP ? ((m / TT) * LTOT + TT + (m % TT)) : m;
            cpa16(sa + r * 128 + cs * 16, A + (size_t)msrc * lda + gcol, va);
            int n = n0 + r; bool vb = n < N;
            cpa16(sb + r * 128 + cs * 16, Bw + (size_t)(vb ? n : 0) * ldw + gcol, vb);
        }
    };

    // prefetch 2 stages
    load_stage(0);
    asm volatile("cp.async.commit_group;\n" ::: "memory");
    if (1 < iters) load_stage(1);
    asm volatile("cp.async.commit_group;\n" ::: "memory");

    for (int it = 0; it < iters; it++) {
        asm volatile("cp.async.wait_group %0;\n" :: "n"(1) : "memory");
        __syncthreads();
        if (it + 2 < iters) load_stage(it + 2);
        asm volatile("cp.async.commit_group;\n" ::: "memory");

        int s = it % GST;
        uint32_t sa = sbase + s * 32768;
        uint32_t sb = sa + 16384;
        #pragma unroll
        for (int h = 0; h < 4; h++) {
            uint32_t ra[4][4];
            #pragma unroll
            for (int i = 0; i < 4; i++) {
                int r = wm * 64 + i * 16 + (lane & 15);
                int c = 2 * h + (lane >> 4);
                ldm4(sa + r * 128 + ((c ^ (r & 7)) * 16), ra[i][0], ra[i][1], ra[i][2], ra[i][3]);
            }
            uint32_t rb[4][2];
            #pragma unroll
            for (int jj = 0; jj < 2; jj++) {
                int t = jj * 2 + (lane >> 4);          // n-tile within warp
                int nr = wn * 32 + t * 8 + (lane & 7);
                int c = 2 * h + ((lane >> 3) & 1);
                uint32_t q0, q1, q2, q3;
                ldm4(sb + nr * 128 + ((c ^ (nr & 7)) * 16), q0, q1, q2, q3);
                rb[jj*2][0] = q0; rb[jj*2][1] = q1;
                rb[jj*2+1][0] = q2; rb[jj*2+1][1] = q3;
            }
            #pragma unroll
            for (int i = 0; i < 4; i++)
                #pragma unroll
                for (int j = 0; j < 4; j++)
                    mma16816(acc[i][j], ra[i], rb[j]);
        }
    }
    asm volatile("cp.async.wait_group %0;\n" :: "n"(0) : "memory");

    // epilogue
    #pragma unroll
    for (int i = 0; i < 4; i++) {
        int rbase = m0 + wm * 64 + i * 16 + (lane >> 2);
        #pragma unroll
        for (int j = 0; j < 4; j++) {
            int col = n0 + wn * 32 + j * 8 + 2 * (lane & 3);
            if (col >= N) continue;
            float b0 = 0.f, b1 = 0.f;
            if (BIAS) { b0 = bias[col]; b1 = bias[col + 1]; }
            #pragma unroll
            for (int half = 0; half < 2; half++) {
                int m = rbase + half * 8;
                if (m >= M) continue;
                float v0 = acc[i][j][half * 2 + 0] + b0;
                float v1 = acc[i][j][half * 2 + 1] + b1;
                if (ACT == 2) {
                    v0 = (v0 > 20.f) ? v0 : log1pf(__expf(v0));
                    v1 = (v1 > 20.f) ? v1 : log1pf(__expf(v1));
                }
                *(float2*)&C[(size_t)m * ldc + col] = make_float2(v0, v1);
            }
        }
    }
}

// ---------------------------------------------------------------------------
// bf16 split conversion kernels
// ---------------------------------------------------------------------------
__global__ void k_wsplit(const float* __restrict__ src, __nv_bfloat16* __restrict__ dst,
                         int N, int K) {
    int idx = blockIdx.x * blockDim.x + threadIdx.x;
    if (idx >= N * K) return;
    int n = idx / K, k = idx - n * K;
    __nv_bfloat16 hi, lo;
    bsplit(src[idx], hi, lo);
    __nv_bfloat16* d = dst + (size_t)n * (3 * K);
    d[k] = hi; d[K + k] = hi; d[2 * K + k] = lo;
}

__global__ void k_asplit(const float* __restrict__ src, int lds,
                         __nv_bfloat16* __restrict__ dst, int R, int K) {
    int idx = blockIdx.x * blockDim.x + threadIdx.x;
    if (idx >= R * K) return;
    int r = idx / K, k = idx - r * K;
    __nv_bfloat16 hi, lo;
    bsplit(src[(size_t)r * lds + k], hi, lo);
    __nv_bfloat16* d = dst + (size_t)r * (3 * K);
    d[k] = hi; d[K + k] = lo; d[2 * K + k] = hi;
}

// split-K reduction for x_proj partials
__global__ void k_red4() {
    int idx = blockIdx.x * blockDim.x + threadIdx.x;
    if (idx >= NROWS * 96) return;
    float s = g_dbcp[idx] + g_dbcp[NROWS*96 + idx]
            + g_dbcp[2*NROWS*96 + idx] + g_dbcp[3*NROWS*96 + idx];
    g_dbc[idx] = s;
}

// ---------------------------------------------------------------------------
// 1. timestep embedding
// ---------------------------------------------------------------------------
__global__ void k_temb(const int* __restrict__ ts) {
    int b = blockIdx.x;
    int i = threadIdx.x;                // 0..511
    float t = (float)ts[b];
    float freq = __expf(-9.210340371976184f * (float)i / 512.0f);
    float arg = t * freq;
    g_temb[b * 1024 + i]       = cosf(arg);
    g_temb[b * 1024 + 512 + i] = sinf(arg);
}

// ---------------------------------------------------------------------------
// 2. small-M (M=4) GEMM for the time MLP
// ---------------------------------------------------------------------------
template<bool SILU>
__global__ void k_smallmm(const float* __restrict__ A,
                          const float* __restrict__ W,
                          const float* __restrict__ bias,
                          float* __restrict__ out, int N, int K) {
    extern __shared__ float sA[];   // 4*K floats
    for (int i = threadIdx.x; i < 4 * K; i += blockDim.x) sA[i] = A[i];
    __syncthreads();
    int w = threadIdx.x >> 5, lane = threadIdx.x & 31;
    int n = blockIdx.x * 8 + w;
    if (n >= N) return;
    const float* Wr = W + (size_t)n * K;
    float a0 = 0.f, a1 = 0.f, a2 = 0.f, a3 = 0.f;
    for (int k = lane * 4; k < K; k += 128) {
        float4 wv = *(const float4*)(Wr + k);
        float4 v0 = *(const float4*)(sA + 0 * K + k);
        float4 v1 = *(const float4*)(sA + 1 * K + k);
        float4 v2 = *(const float4*)(sA + 2 * K + k);
        float4 v3 = *(const float4*)(sA + 3 * K + k);
        a0 += wv.x * v0.x + wv.y * v0.y + wv.z * v0.z + wv.w * v0.w;
        a1 += wv.x * v1.x + wv.y * v1.y + wv.z * v1.z + wv.w * v1.w;
        a2 += wv.x * v2.x + wv.y * v2.y + wv.z * v2.z + wv.w * v2.w;
        a3 += wv.x * v3.x + wv.y * v3.y + wv.z * v3.z + wv.w * v3.w;
    }
    #pragma unroll
    for (int o = 16; o; o >>= 1) {
        a0 += __shfl_xor_sync(0xFFFFFFFFu, a0, o);
        a1 += __shfl_xor_sync(0xFFFFFFFFu, a1, o);
        a2 += __shfl_xor_sync(0xFFFFFFFFu, a2, o);
        a3 += __shfl_xor_sync(0xFFFFFFFFu, a3, o);
    }
    if (lane == 0) {
        float bb = bias[n];
        float r0 = a0 + bb, r1 = a1 + bb, r2 = a2 + bb, r3 = a3 + bb;
        if (SILU) { r0 = siluf(r0); r1 = siluf(r1); r2 = siluf(r2); r3 = siluf(r3); }
        out[0 * N + n] = r0; out[1 * N + n] = r1;
        out[2 * N + n] = r2; out[3 * N + n] = r3;
    }
}

// ---------------------------------------------------------------------------
// 3. build seq (pos + input (+temb), LayerNorm), write rms_norm split to g_xnb
// ---------------------------------------------------------------------------
__global__ void k_build(const float* __restrict__ x_r,
                        const float* __restrict__ motion,
                        const float* __restrict__ pos,
                        const float* __restrict__ ln_g,
                        const float* __restrict__ ln_b,
                        const float* __restrict__ rms_w) {
    int r = blockIdx.x;              // 0..1567
    int b = r / LTOT, l = r % LTOT;
    float v[4];
    #pragma unroll
    for (int j = 0; j < 4; j++) {
        int i = threadIdx.x + j * 256;
        if (l < TT) {
            v[j] = pos[l * DMODEL + i] + motion[((size_t)(b * TT + l)) * DMODEL + i];
        } else {
            int lr = l - TT;
            v[j] = pos[lr * DMODEL + i] + x_r[((size_t)(b * TT + lr)) * DMODEL + i]
                 + g_embt[b * DMODEL + i];
        }
    }
    float s = v[0] + v[1] + v[2] + v[3];
    float sq = v[0]*v[0] + v[1]*v[1] + v[2]*v[2] + v[3]*v[3];
    blockReduce2(s, sq);
    float mu = s * (1.0f / DMODEL);
    float var = sq * (1.0f / DMODEL) - mu * mu;
    float rstd = rsqrtf(var + 1e-5f);
    float nrm[4];
    float s2 = 0.f;
    #pragma unroll
    for (int j = 0; j < 4; j++) {
        int i = threadIdx.x + j * 256;
        nrm[j] = (v[j] - mu) * rstd * ln_g[i] + ln_b[i];
        s2 += nrm[j] * nrm[j];
    }
    float dummy = 0.f;
    blockReduce2(s2, dummy);
    float rr = rsqrtf(s2 * (1.0f / DMODEL) + 1e-5f);
    __nv_bfloat16* xb = g_xnb + (size_t)r * (3 * DMODEL);
    #pragma unroll
    for (int j = 0; j < 4; j++) {
        int i = threadIdx.x + j * 256;
        g_seq[(size_t)r * DMODEL + i] = nrm[j];
        float xn = nrm[j] * rr * rms_w[i];
        __nv_bfloat16 hi, lo;
        bsplit(xn, hi, lo);
        xb[i] = hi; xb[DMODEL + i] = lo; xb[2 * DMODEL + i] = hi;
    }
}

// ---------------------------------------------------------------------------
// 5. causal depthwise conv (k=4) + bias + silu, write fp32 + bf16 split
// ---------------------------------------------------------------------------
__global__ void k_conv(const float* __restrict__ conv_w,
                       const float* __restrict__ conv_b) {
    int idx = blockIdx.x * blockDim.x + threadIdx.x;
    if (idx >= NROWS * DINNER) return;
    int c = idx % DINNER;
    int bl = idx / DINNER;
    int l = bl % LTOT;
    int b = bl / LTOT;
    float w0 = conv_w[c*4+0], w1 = conv_w[c*4+1], w2 = conv_w[c*4+2], w3 = conv_w[c*4+3];
    float acc = conv_b[c];
    size_t base = (size_t)(b * LTOT) * DINNER + c;
    if (l >= 3) acc = fmaf(w0, g_x[base + (size_t)(l-3)*DINNER], acc);
    if (l >= 2) acc = fmaf(w1, g_x[base + (size_t)(l-2)*DINNER], acc);
    if (l >= 1) acc = fmaf(w2, g_x[base + (size_t)(l-1)*DINNER], acc);
    acc = fmaf(w3, g_x[base + (size_t)l*DINNER], acc);
    float xv = siluf(acc);
    g_xc[idx] = xv;
    __nv_bfloat16 hi, lo;
    bsplit(xv, hi, lo);
    __nv_bfloat16* d = g_xcb + (size_t)bl * (3 * DINNER);
    d[c] = hi; d[DINNER + c] = lo; d[2 * DINNER + c] = hi;
}

// ---------------------------------------------------------------------------
// 6. selective scan; emits gated y (l>=196) directly as bf16 A-mode split
// ---------------------------------------------------------------------------
__global__ void k_scan(const float* __restrict__ A_log,
                       const float* __restrict__ Dp) {
    int gt = blockIdx.x * blockDim.x + threadIdx.x;
    int g = gt >> 4;
    int n = threadIdx.x & 15;
    if (g >= BB * DINNER) return;
    int b = g >> 11;
    int e = g & (DINNER - 1);
    float Aen = -__expf(A_log[e * DSTATE + n]);
    float Dpe = Dp[e];
    float h = 0.f;
    for (int l = 0; l < LTOT; l++) {
        int r = b * LTOT + l;
        float d  = g_dlt[(size_t)r * DINNER + e];
        float x  = g_xc [(size_t)r * DINNER + e];
        float Bn = g_dbc[r * 96 + 64 + n];
        float Cn = g_dbc[r * 96 + 80 + n];
        float dA = __expf(d * Aen);
        h = fmaf(dA, h, d * Bn * x);
        float yv = h * Cn;
        #pragma unroll
        for (int o = 8; o; o >>= 1) yv += __shfl_xor_sync(0xFFFFFFFFu, yv, o);
        if (n == 0 && l >= TT) {
            int rc = b * TT + (l - TT);
            float z = g_z[(size_t)rc * DINNER + e];
            float yo = (yv + x * Dpe) * siluf(z);
            __nv_bfloat16 hi, lo;
            bsplit(yo, hi, lo);
            __nv_bfloat16* dst = g_ycb + (size_t)rc * (3 * DINNER);
            dst[e] = hi; dst[DINNER + e] = lo; dst[2 * DINNER + e] = hi;
        }
    }
}

// ---------------------------------------------------------------------------
// 7. final: out = LayerNorm(seq[:,196:] + out_proj_result)
// ---------------------------------------------------------------------------
__global__ void k_final(const float* __restrict__ ln_g,
                        const float* __restrict__ ln_b,
                        float* __restrict__ out) {
    int r = blockIdx.x;           // 0..783
    int b = r / TT, l = r % TT;
    size_t seqrow = (size_t)(b * LTOT + TT + l) * DMODEL;
    float v[4];
    #pragma unroll
    for (int j = 0; j < 4; j++) {
        int i = threadIdx.x + j * 256;
        v[j] = g_seq[seqrow + i] + g_mo[(size_t)r * DMODEL + i];
    }
    float s = v[0] + v[1] + v[2] + v[3];
    float sq = v[0]*v[0] + v[1]*v[1] + v[2]*v[2] + v[3]*v[3];
    blockReduce2(s, sq);
    float mu = s * (1.0f / DMODEL);
    float var = sq * (1.0f / DMODEL) - mu * mu;
    float rstd = rsqrtf(var + 1e-5f);
    #pragma unroll
    for (int j = 0; j < 4; j++) {
        int i = threadIdx.x + j * 256;
        out[(size_t)r * DMODEL + i] = (v[j] - mu) * rstd * ln_g[i] + ln_b[i];
    }
}

// ---------------------------------------------------------------------------
// Launch
// ---------------------------------------------------------------------------
extern "C" void kernel_launch(void* const* d_in, const int* in_sizes, int n_in,
                              void* d_out, int out_size) {
    const float* x_r      = (const float*)d_in[0];
    const int*   ts       = (const int*)  d_in[1];
    const float* motion   = (const float*)d_in[2];
    const float* time_w1  = (const float*)d_in[3];
    const float* time_b1  = (const float*)d_in[4];
    const float* time_w2  = (const float*)d_in[5];
    const float* time_b2  = (const float*)d_in[6];
    const float* pos_emb  = (const float*)d_in[7];
    const float* ln_g     = (const float*)d_in[8];
    const float* ln_b     = (const float*)d_in[9];
    const float* in_proj  = (const float*)d_in[10];
    const float* conv_w   = (const float*)d_in[11];
    const float* conv_b   = (const float*)d_in[12];
    const float* x_proj   = (const float*)d_in[13];
    const float* dt_w     = (const float*)d_in[14];
    const float* dt_b     = (const float*)d_in[15];
    const float* A_log    = (const float*)d_in[16];
    const float* Dp       = (const float*)d_in[17];
    const float* out_proj = (const float*)d_in[18];
    const float* rms_w    = (const float*)d_in[19];
    float* out = (float*)d_out;

    float *p_temb, *p_h, *p_embt, *p_x, *p_z, *p_dbcp, *p_dbc, *p_dlt, *p_mo;
    __nv_bfloat16 *p_xnb, *p_ipb, *p_xcb, *p_xpb, *p_dtb, *p_dtwb, *p_ycb, *p_opb;
    cudaGetSymbolAddress((void**)&p_temb, g_temb);
    cudaGetSymbolAddress((void**)&p_h,    g_h);
    cudaGetSymbolAddress((void**)&p_embt, g_embt);
    cudaGetSymbolAddress((void**)&p_x,    g_x);
    cudaGetSymbolAddress((void**)&p_z,    g_z);
    cudaGetSymbolAddress((void**)&p_dbcp, g_dbcp);
    cudaGetSymbolAddress((void**)&p_dbc,  g_dbc);
    cudaGetSymbolAddress((void**)&p_dlt,  g_dlt);
    cudaGetSymbolAddress((void**)&p_mo,   g_mo);
    cudaGetSymbolAddress((void**)&p_xnb,  g_xnb);
    cudaGetSymbolAddress((void**)&p_ipb,  g_ipb);
    cudaGetSymbolAddress((void**)&p_xcb,  g_xcb);
    cudaGetSymbolAddress((void**)&p_xpb,  g_xpb);
    cudaGetSymbolAddress((void**)&p_dtb,  g_dtb);
    cudaGetSymbolAddress((void**)&p_dtwb, g_dtwb);
    cudaGetSymbolAddress((void**)&p_ycb,  g_ycb);
    cudaGetSymbolAddress((void**)&p_opb,  g_opb);

    cudaFuncSetAttribute(gemm_bf16<0,false,false>, cudaFuncAttributeMaxDynamicSharedMemorySize, GSMEM_BYTES);
    cudaFuncSetAttribute(gemm_bf16<0,false,true >, cudaFuncAttributeMaxDynamicSharedMemorySize, GSMEM_BYTES);
    cudaFuncSetAttribute(gemm_bf16<2,true ,false>, cudaFuncAttributeMaxDynamicSharedMemorySize, GSMEM_BYTES);

    // weight splits (independent of data path)
    k_wsplit<<<(4096*1024 + 255)/256, 256>>>(in_proj,  p_ipb, 4096, 1024);
    k_wsplit<<<(96*2048   + 255)/256, 256>>>(x_proj,   p_xpb, 96,   2048);
    k_wsplit<<<(2048*64   + 255)/256, 256>>>(dt_w,     p_dtwb, 2048, 64);
    k_wsplit<<<(1024*2048 + 255)/256, 256>>>(out_proj, p_opb, 1024, 2048);

    // 1-2. time embedding + MLP
    k_temb<<<BB, 512>>>(ts);
    k_smallmm<true ><<<2048/8, 256, 4*1024*sizeof(float)>>>(p_temb, time_w1, time_b1, p_h, 2048, 1024);
    k_smallmm<false><<<1024/8, 256, 4*2048*sizeof(float)>>>(p_h,    time_w2, time_b2, p_embt, 1024, 2048);

    // 3. build seq (LN) + rms-norm split
    k_build<<<NROWS, 256>>>(x_r, motion, pos_emb, ln_g, ln_b, rms_w);

    // 4a. in_proj x-half: g_x[1568,2048] = xnb @ ipb[0:2048]^T   (K' = 3072)
    {
        dim3 grid(2048/128, (NROWS + 127)/128, 1);
        gemm_bf16<0,false,false><<<grid, 256, GSMEM_BYTES>>>(
            p_xnb, 3*DMODEL, p_ipb, 3*DMODEL, nullptr,
            p_x, DINNER, NROWS, DINNER, 3*DMODEL);
    }
    // 4b. in_proj z-half, only rows l>=196: g_z[784,2048] = xnb[map] @ ipb[2048:]^T
    {
        dim3 grid(2048/128, (NOUT + 127)/128, 1);
        gemm_bf16<0,false,true><<<grid, 256, GSMEM_BYTES>>>(
            p_xnb, 3*DMODEL, p_ipb + (size_t)DINNER * 3*DMODEL, 3*DMODEL, nullptr,
            p_z, DINNER, NOUT, DINNER, 3*DMODEL);
    }

    // 5. conv + silu + split
    k_conv<<<(NROWS*DINNER + 255)/256, 256>>>(conv_w, conv_b);

    // 6. x_proj split-K=4: dbcp[z][1568,96] = xcb[:, z*1536:(z+1)*1536] @ xpb^T
    {
        dim3 grid(1, (NROWS + 127)/128, KSPLIT);
        gemm_bf16<0,false,false><<<grid, 256, GSMEM_BYTES>>>(
            p_xcb, 3*DINNER, p_xpb, 3*DINNER, nullptr,
            p_dbcp, 96, NROWS, 96, (3*DINNER)/KSPLIT);
    }
    k_red4<<<(NROWS*96 + 255)/256, 256>>>();

    // 7. dt input split + dt_proj: dlt = softplus(dtb @ dtwb^T + dt_b)  (K' = 192)
    k_asplit<<<(NROWS*64 + 255)/256, 256>>>(p_dbc, 96, p_dtb, NROWS, 64);
    {
        dim3 grid(2048/128, (NROWS + 127)/128, 1);
        gemm_bf16<2,true,false><<<grid, 256, GSMEM_BYTES>>>(
            p_dtb, 3*DTRANK, p_dtwb, 3*DTRANK, dt_b,
            p_dlt, DINNER, NROWS, DINNER, 3*DTRANK);
    }

    // 8. selective scan (writes bf16 split g_ycb directly)
    k_scan<<<(BB*DINNER*16 + 255)/256, 256>>>(A_log, Dp);

    // 9. out_proj: mo[784,1024] = ycb @ opb^T  (K' = 6144)
    {
        dim3 grid(1024/128, (NOUT + 127)/128, 1);
        gemm_bf16<0,false,false><<<grid, 256, GSMEM_BYTES>>>(
            p_ycb, 3*DINNER, p_opb, 3*DINNER, nullptr,
            p_mo, DMODEL, NOUT, DMODEL, 3*DINNER);
    }

    // 10. residual + final LN -> d_out
    k_final<<<NOUT, 256>>>(ln_g, ln_b, out);
}

// round 12
// speedup vs baseline: 2.8834x; 1.0684x over previous
#include <cuda_runtime.h>
#include <cuda_bf16.h>
#include <math.h>
#include <stdint.h>

// ---------------------------------------------------------------------------
// Problem constants
// ---------------------------------------------------------------------------
#define BB 4
#define TT 196
#define LTOT 392            // TM + T
#define DMODEL 1024
#define DINNER 2048
#define DSTATE 16
#define DCONV 4
#define DTRANK 64
#define NROWS (BB*LTOT)     // 1568
#define NOUT  (BB*TT)       // 784
#define KS_XP 8             // x_proj split-K
#define KS_Z  2             // z-GEMM split-K
#define KS_OP 4             // out_proj split-K

// ---------------------------------------------------------------------------
// Device scratch (static: no allocations allowed)
// ---------------------------------------------------------------------------
__device__ float g_temb[BB * 1024];
__device__ float g_h   [BB * 2048];
__device__ float g_embt[BB * 1024];
__device__ float g_seq [NROWS * DMODEL];       // LN'ed concat sequence
__device__ float g_x   [NROWS * DINNER];       // in_proj x-half (pre conv)
__device__ float g_zp  [KS_Z * NOUT * DINNER]; // z-GEMM split-K partials
__device__ float g_z   [NOUT  * DINNER];       // in_proj z-half, l>=196 compact
__device__ float g_xc  [NROWS * DINNER];       // silu(conv(x))
__device__ float g_dbcp[KS_XP * NROWS * 96];   // x_proj split-K partials
__device__ float g_dbc [NROWS * 96];           // x_proj out (dt|B|C)
__device__ float g_dlt [NROWS * DINNER];       // softplus(dt_proj)
__device__ float g_mop [KS_OP * NOUT * DMODEL];// out_proj split-K partials

// bf16 split operand buffers (K' = 3K): A-mode = [hi|lo|hi], W-mode = [hi|hi|lo]
__device__ __nv_bfloat16 g_xnb [NROWS * 3*DMODEL];   // rms_norm(seq), A-mode
__device__ __nv_bfloat16 g_ipb [4096  * 3*DMODEL];   // in_proj_w, W-mode
__device__ __nv_bfloat16 g_xcb [NROWS * 3*DINNER];   // xc, A-mode
__device__ __nv_bfloat16 g_xpb [96    * 3*DINNER];   // x_proj_w, W-mode
__device__ __nv_bfloat16 g_dtb [NROWS * 3*DTRANK];   // dbc[:, :64], A-mode
__device__ __nv_bfloat16 g_dtwb[DINNER* 3*DTRANK];   // dt_proj_w, W-mode
__device__ __nv_bfloat16 g_ycb [NOUT  * 3*DINNER];   // scan out, A-mode
__device__ __nv_bfloat16 g_opb [DMODEL* 3*DINNER];   // out_proj_w, W-mode

// ---------------------------------------------------------------------------
// Helpers
// ---------------------------------------------------------------------------
__device__ __forceinline__ float siluf(float x) {
    return x / (1.0f + __expf(-x));
}

__device__ __forceinline__ void bsplit(float x, __nv_bfloat16& hi, __nv_bfloat16& lo) {
    hi = __float2bfloat16(x);
    lo = __float2bfloat16(x - __bfloat162float(hi));
}

__device__ __forceinline__ void blockReduce2(float& a, float& b) {
    __shared__ float s[66];
    #pragma unroll
    for (int o = 16; o; o >>= 1) {
        a += __shfl_xor_sync(0xFFFFFFFFu, a, o);
        b += __shfl_xor_sync(0xFFFFFFFFu, b, o);
    }
    int w = threadIdx.x >> 5, lane = threadIdx.x & 31;
    if (lane == 0) { s[w] = a; s[32 + w] = b; }
    __syncthreads();
    if (threadIdx.x == 0) {
        float sa = 0.f, sb = 0.f;
        int nw = blockDim.x >> 5;
        for (int i = 0; i < nw; i++) { sa += s[i]; sb += s[32 + i]; }
        s[64] = sa; s[65] = sb;
    }
    __syncthreads();
    a = s[64]; b = s[65];
    __syncthreads();
}

// ---------------------------------------------------------------------------
// mma.sync building blocks
// ---------------------------------------------------------------------------
__device__ __forceinline__ void cpa16(uint32_t d, const void* g, bool v) {
    int sz = v ? 16 : 0;
    asm volatile("cp.async.cg.shared.global [%0], [%1], 16, %2;\n"
                 :: "r"(d), "l"(g), "r"(sz));
}
__device__ __forceinline__ void ldm4(uint32_t a, uint32_t& r0, uint32_t& r1,
                                     uint32_t& r2, uint32_t& r3) {
    asm volatile("ldmatrix.sync.aligned.m8n8.x4.shared.b16 {%0,%1,%2,%3}, [%4];"
                 : "=r"(r0), "=r"(r1), "=r"(r2), "=r"(r3) : "r"(a));
}
__device__ __forceinline__ void mma16816(float* c, const uint32_t* a, const uint32_t* b) {
    asm volatile(
        "mma.sync.aligned.m16n8k16.row.col.f32.bf16.bf16.f32 "
        "{%0,%1,%2,%3},{%4,%5,%6,%7},{%8,%9},{%0,%1,%2,%3};"
        : "+f"(c[0]), "+f"(c[1]), "+f"(c[2]), "+f"(c[3])
        : "r"(a[0]), "r"(a[1]), "r"(a[2]), "r"(a[3]), "r"(b[0]), "r"(b[1]));
}

// ---------------------------------------------------------------------------
// bf16 tensor-core GEMM: C[M,N] = act(A[M,K(lda)] @ W[N,K(ldw)]^T (+bias))
//   128x128 CTA tile, 8 warps (2x4) of 64x32, BK=64, 3-stage cp.async.
//   K must be a multiple of 64. gridDim.z = split-K count: slice z handles
//   K columns [z*K, (z+1)*K) of A/W (koff = z*K) and writes C + z*M*ldc.
//   AMAP: A row m reads source row (m/196)*392 + 196 + m%196.
//   ACT: 0 none, 2 softplus
// ---------------------------------------------------------------------------
#define GST 3
#define GSMEM_BYTES (GST * 32768)

template<int ACT, bool BIAS, bool AMAP>
__global__ void __launch_bounds__(256, 2)
gemm_bf16(const __nv_bfloat16* __restrict__ A, int lda,
          const __nv_bfloat16* __restrict__ Bw, int ldw,
          const float* __restrict__ bias, float* __restrict__ C, int ldc,
          int M, int N, int K) {
    extern __shared__ __nv_bfloat16 smem[];
    uint32_t sbase = (uint32_t)__cvta_generic_to_shared(smem);
    const int tid = threadIdx.x;
    const int wid = tid >> 5, lane = tid & 31;
    const int wm = wid >> 2, wn = wid & 3;         // 2 x 4 warp grid
    const int m0 = blockIdx.y * 128, n0 = blockIdx.x * 128;
    const int koff = blockIdx.z * K;
    C += (size_t)blockIdx.z * M * ldc;
    const int iters = K >> 6;

    float acc[4][4][4];
    #pragma unroll
    for (int i = 0; i < 4; i++)
        #pragma unroll
        for (int j = 0; j < 4; j++)
            #pragma unroll
            for (int q = 0; q < 4; q++) acc[i][j][q] = 0.f;

    auto load_stage = [&](int t) {
        int s = t % GST;
        uint32_t sa = sbase + s * 32768;
        uint32_t sb = sa + 16384;
        #pragma unroll
        for (int q = 0; q < 4; q++) {
            int cid = tid + q * 256;           // 0..1023
            int r = cid >> 3, c = cid & 7;
            int cs = c ^ (r & 7);
            int gcol = koff + t * 64 + c * 8;
            int m = m0 + r; bool va = m < M;
            int msrc = 0;
            if (va) msrc = AMAP ? ((m / TT) * LTOT + TT + (m % TT)) : m;
            cpa16(sa + r * 128 + cs * 16, A + (size_t)msrc * lda + gcol, va);
            int n = n0 + r; bool vb = n < N;
            cpa16(sb + r * 128 + cs * 16, Bw + (size_t)(vb ? n : 0) * ldw + gcol, vb);
        }
    };

    // prefetch 2 stages
    load_stage(0);
    asm volatile("cp.async.commit_group;\n" ::: "memory");
    if (1 < iters) load_stage(1);
    asm volatile("cp.async.commit_group;\n" ::: "memory");

    for (int it = 0; it < iters; it++) {
        asm volatile("cp.async.wait_group %0;\n" :: "n"(1) : "memory");
        __syncthreads();
        if (it + 2 < iters) load_stage(it + 2);
        asm volatile("cp.async.commit_group;\n" ::: "memory");

        int s = it % GST;
        uint32_t sa = sbase + s * 32768;
        uint32_t sb = sa + 16384;
        #pragma unroll
        for (int h = 0; h < 4; h++) {
            uint32_t ra[4][4];
            #pragma unroll
            for (int i = 0; i < 4; i++) {
                int r = wm * 64 + i * 16 + (lane & 15);
                int c = 2 * h + (lane >> 4);
                ldm4(sa + r * 128 + ((c ^ (r & 7)) * 16), ra[i][0], ra[i][1], ra[i][2], ra[i][3]);
            }
            uint32_t rb[4][2];
            #pragma unroll
            for (int jj = 0; jj < 2; jj++) {
                int t = jj * 2 + (lane >> 4);          // n-tile within warp
                int nr = wn * 32 + t * 8 + (lane & 7);
                int c = 2 * h + ((lane >> 3) & 1);
                uint32_t q0, q1, q2, q3;
                ldm4(sb + nr * 128 + ((c ^ (nr & 7)) * 16), q0, q1, q2, q3);
                rb[jj*2][0] = q0; rb[jj*2][1] = q1;
                rb[jj*2+1][0] = q2; rb[jj*2+1][1] = q3;
            }
            #pragma unroll
            for (int i = 0; i < 4; i++)
                #pragma unroll
                for (int j = 0; j < 4; j++)
                    mma16816(acc[i][j], ra[i], rb[j]);
        }
    }
    asm volatile("cp.async.wait_group %0;\n" :: "n"(0) : "memory");

    // epilogue
    #pragma unroll
    for (int i = 0; i < 4; i++) {
        int rbase = m0 + wm * 64 + i * 16 + (lane >> 2);
        #pragma unroll
        for (int j = 0; j < 4; j++) {
            int col = n0 + wn * 32 + j * 8 + 2 * (lane & 3);
            if (col >= N) continue;
            float b0 = 0.f, b1 = 0.f;
            if (BIAS) { b0 = bias[col]; b1 = bias[col + 1]; }
            #pragma unroll
            for (int half = 0; half < 2; half++) {
                int m = rbase + half * 8;
                if (m >= M) continue;
                float v0 = acc[i][j][half * 2 + 0] + b0;
                float v1 = acc[i][j][half * 2 + 1] + b1;
                if (ACT == 2) {
                    v0 = (v0 > 20.f) ? v0 : log1pf(__expf(v0));
                    v1 = (v1 > 20.f) ? v1 : log1pf(__expf(v1));
                }
                *(float2*)&C[(size_t)m * ldc + col] = make_float2(v0, v1);
            }
        }
    }
}

// ---------------------------------------------------------------------------
// bf16 split conversion kernels
// ---------------------------------------------------------------------------
__global__ void k_wsplit(const float* __restrict__ src, __nv_bfloat16* __restrict__ dst,
                         int N, int K) {
    int idx = blockIdx.x * blockDim.x + threadIdx.x;
    if (idx >= N * K) return;
    int n = idx / K, k = idx - n * K;
    __nv_bfloat16 hi, lo;
    bsplit(src[idx], hi, lo);
    __nv_bfloat16* d = dst + (size_t)n * (3 * K);
    d[k] = hi; d[K + k] = hi; d[2 * K + k] = lo;
}

__global__ void k_asplit(const float* __restrict__ src, int lds,
                         __nv_bfloat16* __restrict__ dst, int R, int K) {
    int idx = blockIdx.x * blockDim.x + threadIdx.x;
    if (idx >= R * K) return;
    int r = idx / K, k = idx - r * K;
    __nv_bfloat16 hi, lo;
    bsplit(src[(size_t)r * lds + k], hi, lo);
    __nv_bfloat16* d = dst + (size_t)r * (3 * K);
    d[k] = hi; d[K + k] = lo; d[2 * K + k] = hi;
}

// generic split-K partial reduction: dst[i] = sum_s src[s*stride + i]
__global__ void k_redsum(const float* __restrict__ src, float* __restrict__ dst,
                         int n, int nslices, int stride) {
    int idx = blockIdx.x * blockDim.x + threadIdx.x;
    if (idx >= n) return;
    float s = 0.f;
    for (int z = 0; z < nslices; z++) s += src[(size_t)z * stride + idx];
    dst[idx] = s;
}

// ---------------------------------------------------------------------------
// 1. timestep embedding
// ---------------------------------------------------------------------------
__global__ void k_temb(const int* __restrict__ ts) {
    int b = blockIdx.x;
    int i = threadIdx.x;                // 0..511
    float t = (float)ts[b];
    float freq = __expf(-9.210340371976184f * (float)i / 512.0f);
    float arg = t * freq;
    g_temb[b * 1024 + i]       = cosf(arg);
    g_temb[b * 1024 + 512 + i] = sinf(arg);
}

// ---------------------------------------------------------------------------
// 2. small-M (M=4) GEMM for the time MLP
// ---------------------------------------------------------------------------
template<bool SILU>
__global__ void k_smallmm(const float* __restrict__ A,
                          const float* __restrict__ W,
                          const float* __restrict__ bias,
                          float* __restrict__ out, int N, int K) {
    extern __shared__ float sA[];   // 4*K floats
    for (int i = threadIdx.x; i < 4 * K; i += blockDim.x) sA[i] = A[i];
    __syncthreads();
    int w = threadIdx.x >> 5, lane = threadIdx.x & 31;
    int n = blockIdx.x * 8 + w;
    if (n >= N) return;
    const float* Wr = W + (size_t)n * K;
    float a0 = 0.f, a1 = 0.f, a2 = 0.f, a3 = 0.f;
    for (int k = lane * 4; k < K; k += 128) {
        float4 wv = *(const float4*)(Wr + k);
        float4 v0 = *(const float4*)(sA + 0 * K + k);
        float4 v1 = *(const float4*)(sA + 1 * K + k);
        float4 v2 = *(const float4*)(sA + 2 * K + k);
        float4 v3 = *(const float4*)(sA + 3 * K + k);
        a0 += wv.x * v0.x + wv.y * v0.y + wv.z * v0.z + wv.w * v0.w;
        a1 += wv.x * v1.x + wv.y * v1.y + wv.z * v1.z + wv.w * v1.w;
        a2 += wv.x * v2.x + wv.y * v2.y + wv.z * v2.z + wv.w * v2.w;
        a3 += wv.x * v3.x + wv.y * v3.y + wv.z * v3.z + wv.w * v3.w;
    }
    #pragma unroll
    for (int o = 16; o; o >>= 1) {
        a0 += __shfl_xor_sync(0xFFFFFFFFu, a0, o);
        a1 += __shfl_xor_sync(0xFFFFFFFFu, a1, o);
        a2 += __shfl_xor_sync(0xFFFFFFFFu, a2, o);
        a3 += __shfl_xor_sync(0xFFFFFFFFu, a3, o);
    }
    if (lane == 0) {
        float bb = bias[n];
        float r0 = a0 + bb, r1 = a1 + bb, r2 = a2 + bb, r3 = a3 + bb;
        if (SILU) { r0 = siluf(r0); r1 = siluf(r1); r2 = siluf(r2); r3 = siluf(r3); }
        out[0 * N + n] = r0; out[1 * N + n] = r1;
        out[2 * N + n] = r2; out[3 * N + n] = r3;
    }
}

// ---------------------------------------------------------------------------
// 3. build seq (pos + input (+temb), LayerNorm), write rms_norm split to g_xnb
// ---------------------------------------------------------------------------
__global__ void k_build(const float* __restrict__ x_r,
                        const float* __restrict__ motion,
                        const float* __restrict__ pos,
                        const float* __restrict__ ln_g,
                        const float* __restrict__ ln_b,
                        const float* __restrict__ rms_w) {
    int r = blockIdx.x;              // 0..1567
    int b = r / LTOT, l = r % LTOT;
    float v[4];
    #pragma unroll
    for (int j = 0; j < 4; j++) {
        int i = threadIdx.x + j * 256;
        if (l < TT) {
            v[j] = pos[l * DMODEL + i] + motion[((size_t)(b * TT + l)) * DMODEL + i];
        } else {
            int lr = l - TT;
            v[j] = pos[lr * DMODEL + i] + x_r[((size_t)(b * TT + lr)) * DMODEL + i]
                 + g_embt[b * DMODEL + i];
        }
    }
    float s = v[0] + v[1] + v[2] + v[3];
    float sq = v[0]*v[0] + v[1]*v[1] + v[2]*v[2] + v[3]*v[3];
    blockReduce2(s, sq);
    float mu = s * (1.0f / DMODEL);
    float var = sq * (1.0f / DMODEL) - mu * mu;
    float rstd = rsqrtf(var + 1e-5f);
    float nrm[4];
    float s2 = 0.f;
    #pragma unroll
    for (int j = 0; j < 4; j++) {
        int i = threadIdx.x + j * 256;
        nrm[j] = (v[j] - mu) * rstd * ln_g[i] + ln_b[i];
        s2 += nrm[j] * nrm[j];
    }
    float dummy = 0.f;
    blockReduce2(s2, dummy);
    float rr = rsqrtf(s2 * (1.0f / DMODEL) + 1e-5f);
    __nv_bfloat16* xb = g_xnb + (size_t)r * (3 * DMODEL);
    #pragma unroll
    for (int j = 0; j < 4; j++) {
        int i = threadIdx.x + j * 256;
        g_seq[(size_t)r * DMODEL + i] = nrm[j];
        float xn = nrm[j] * rr * rms_w[i];
        __nv_bfloat16 hi, lo;
        bsplit(xn, hi, lo);
        xb[i] = hi; xb[DMODEL + i] = lo; xb[2 * DMODEL + i] = hi;
    }
}

// ---------------------------------------------------------------------------
// 5. causal depthwise conv (k=4) + bias + silu, write fp32 + bf16 split
// ---------------------------------------------------------------------------
__global__ void k_conv(const float* __restrict__ conv_w,
                       const float* __restrict__ conv_b) {
    int idx = blockIdx.x * blockDim.x + threadIdx.x;
    if (idx >= NROWS * DINNER) return;
    int c = idx % DINNER;
    int bl = idx / DINNER;
    int l = bl % LTOT;
    int b = bl / LTOT;
    float w0 = conv_w[c*4+0], w1 = conv_w[c*4+1], w2 = conv_w[c*4+2], w3 = conv_w[c*4+3];
    float acc = conv_b[c];
    size_t base = (size_t)(b * LTOT) * DINNER + c;
    if (l >= 3) acc = fmaf(w0, g_x[base + (size_t)(l-3)*DINNER], acc);
    if (l >= 2) acc = fmaf(w1, g_x[base + (size_t)(l-2)*DINNER], acc);
    if (l >= 1) acc = fmaf(w2, g_x[base + (size_t)(l-1)*DINNER], acc);
    acc = fmaf(w3, g_x[base + (size_t)l*DINNER], acc);
    float xv = siluf(acc);
    g_xc[idx] = xv;
    __nv_bfloat16 hi, lo;
    bsplit(xv, hi, lo);
    __nv_bfloat16* d = g_xcb + (size_t)bl * (3 * DINNER);
    d[c] = hi; d[DINNER + c] = lo; d[2 * DINNER + c] = hi;
}

// ---------------------------------------------------------------------------
// 6. selective scan; emits gated y (l>=196) directly as bf16 A-mode split
// ---------------------------------------------------------------------------
__global__ void k_scan(const float* __restrict__ A_log,
                       const float* __restrict__ Dp) {
    int gt = blockIdx.x * blockDim.x + threadIdx.x;
    int g = gt >> 4;
    int n = threadIdx.x & 15;
    if (g >= BB * DINNER) return;
    int b = g >> 11;
    int e = g & (DINNER - 1);
    float Aen = -__expf(A_log[e * DSTATE + n]);
    float Dpe = Dp[e];
    float h = 0.f;
    for (int l = 0; l < LTOT; l++) {
        int r = b * LTOT + l;
        float d  = g_dlt[(size_t)r * DINNER + e];
        float x  = g_xc [(size_t)r * DINNER + e];
        float Bn = g_dbc[r * 96 + 64 + n];
        float Cn = g_dbc[r * 96 + 80 + n];
        float dA = __expf(d * Aen);
        h = fmaf(dA, h, d * Bn * x);
        float yv = h * Cn;
        #pragma unroll
        for (int o = 8; o; o >>= 1) yv += __shfl_xor_sync(0xFFFFFFFFu, yv, o);
        if (n == 0 && l >= TT) {
            int rc = b * TT + (l - TT);
            float z = g_z[(size_t)rc * DINNER + e];
            float yo = (yv + x * Dpe) * siluf(z);
            __nv_bfloat16 hi, lo;
            bsplit(yo, hi, lo);
            __nv_bfloat16* dst = g_ycb + (size_t)rc * (3 * DINNER);
            dst[e] = hi; dst[DINNER + e] = lo; dst[2 * DINNER + e] = hi;
        }
    }
}

// ---------------------------------------------------------------------------
// 7. final: out = LayerNorm(seq[:,196:] + sum_z mop[z])
// ---------------------------------------------------------------------------
__global__ void k_final(const float* __restrict__ ln_g,
                        const float* __restrict__ ln_b,
                        float* __restrict__ out) {
    int r = blockIdx.x;           // 0..783
    int b = r / TT, l = r % TT;
    size_t seqrow = (size_t)(b * LTOT + TT + l) * DMODEL;
    const size_t mstride = (size_t)NOUT * DMODEL;
    float v[4];
    #pragma unroll
    for (int j = 0; j < 4; j++) {
        int i = threadIdx.x + j * 256;
        size_t mi = (size_t)r * DMODEL + i;
        float mo = g_mop[mi] + g_mop[mstride + mi]
                 + g_mop[2 * mstride + mi] + g_mop[3 * mstride + mi];
        v[j] = g_seq[seqrow + i] + mo;
    }
    float s = v[0] + v[1] + v[2] + v[3];
    float sq = v[0]*v[0] + v[1]*v[1] + v[2]*v[2] + v[3]*v[3];
    blockReduce2(s, sq);
    float mu = s * (1.0f / DMODEL);
    float var = sq * (1.0f / DMODEL) - mu * mu;
    float rstd = rsqrtf(var + 1e-5f);
    #pragma unroll
    for (int j = 0; j < 4; j++) {
        int i = threadIdx.x + j * 256;
        out[(size_t)r * DMODEL + i] = (v[j] - mu) * rstd * ln_g[i] + ln_b[i];
    }
}

// ---------------------------------------------------------------------------
// Launch
// ---------------------------------------------------------------------------
extern "C" void kernel_launch(void* const* d_in, const int* in_sizes, int n_in,
                              void* d_out, int out_size) {
    const float* x_r      = (const float*)d_in[0];
    const int*   ts       = (const int*)  d_in[1];
    const float* motion   = (const float*)d_in[2];
    const float* time_w1  = (const float*)d_in[3];
    const float* time_b1  = (const float*)d_in[4];
    const float* time_w2  = (const float*)d_in[5];
    const float* time_b2  = (const float*)d_in[6];
    const float* pos_emb  = (const float*)d_in[7];
    const float* ln_g     = (const float*)d_in[8];
    const float* ln_b     = (const float*)d_in[9];
    const float* in_proj  = (const float*)d_in[10];
    const float* conv_w   = (const float*)d_in[11];
    const float* conv_b   = (const float*)d_in[12];
    const float* x_proj   = (const float*)d_in[13];
    const float* dt_w     = (const float*)d_in[14];
    const float* dt_b     = (const float*)d_in[15];
    const float* A_log    = (const float*)d_in[16];
    const float* Dp       = (const float*)d_in[17];
    const float* out_proj = (const float*)d_in[18];
    const float* rms_w    = (const float*)d_in[19];
    float* out = (float*)d_out;

    float *p_temb, *p_h, *p_embt, *p_x, *p_zp, *p_z, *p_dbcp, *p_dbc, *p_dlt, *p_mop;
    __nv_bfloat16 *p_xnb, *p_ipb, *p_xcb, *p_xpb, *p_dtb, *p_dtwb, *p_ycb, *p_opb;
    cudaGetSymbolAddress((void**)&p_temb, g_temb);
    cudaGetSymbolAddress((void**)&p_h,    g_h);
    cudaGetSymbolAddress((void**)&p_embt, g_embt);
    cudaGetSymbolAddress((void**)&p_x,    g_x);
    cudaGetSymbolAddress((void**)&p_zp,   g_zp);
    cudaGetSymbolAddress((void**)&p_z,    g_z);
    cudaGetSymbolAddress((void**)&p_dbcp, g_dbcp);
    cudaGetSymbolAddress((void**)&p_dbc,  g_dbc);
    cudaGetSymbolAddress((void**)&p_dlt,  g_dlt);
    cudaGetSymbolAddress((void**)&p_mop,  g_mop);
    cudaGetSymbolAddress((void**)&p_xnb,  g_xnb);
    cudaGetSymbolAddress((void**)&p_ipb,  g_ipb);
    cudaGetSymbolAddress((void**)&p_xcb,  g_xcb);
    cudaGetSymbolAddress((void**)&p_xpb,  g_xpb);
    cudaGetSymbolAddress((void**)&p_dtb,  g_dtb);
    cudaGetSymbolAddress((void**)&p_dtwb, g_dtwb);
    cudaGetSymbolAddress((void**)&p_ycb,  g_ycb);
    cudaGetSymbolAddress((void**)&p_opb,  g_opb);

    cudaFuncSetAttribute(gemm_bf16<0,false,false>, cudaFuncAttributeMaxDynamicSharedMemorySize, GSMEM_BYTES);
    cudaFuncSetAttribute(gemm_bf16<0,false,true >, cudaFuncAttributeMaxDynamicSharedMemorySize, GSMEM_BYTES);
    cudaFuncSetAttribute(gemm_bf16<2,true ,false>, cudaFuncAttributeMaxDynamicSharedMemorySize, GSMEM_BYTES);

    // Launch order puts the in_proj x-GEMM at position 6 so ncu (-s 5 -c 1)
    // captures it instead of an elementwise kernel.

    // [1] in_proj weight split (needed by launches 6-7)
    k_wsplit<<<(4096*1024 + 255)/256, 256>>>(in_proj,  p_ipb, 4096, 1024);

    // [2-4] time embedding + MLP
    k_temb<<<BB, 512>>>(ts);
    k_smallmm<true ><<<2048/8, 256, 4*1024*sizeof(float)>>>(p_temb, time_w1, time_b1, p_h, 2048, 1024);
    k_smallmm<false><<<1024/8, 256, 4*2048*sizeof(float)>>>(p_h,    time_w2, time_b2, p_embt, 1024, 2048);

    // [5] build seq (LN) + rms-norm split
    k_build<<<NROWS, 256>>>(x_r, motion, pos_emb, ln_g, ln_b, rms_w);

    // [6] in_proj x-half: g_x[1568,2048] = xnb @ ipb[0:2048]^T   (K' = 3072)
    {
        dim3 grid(2048/128, (NROWS + 127)/128, 1);
        gemm_bf16<0,false,false><<<grid, 256, GSMEM_BYTES>>>(
            p_xnb, 3*DMODEL, p_ipb, 3*DMODEL, nullptr,
            p_x, DINNER, NROWS, DINNER, 3*DMODEL);
    }
    // [7] in_proj z-half, rows l>=196, split-K=2: zp[s][784,2048]
    {
        dim3 grid(2048/128, (NOUT + 127)/128, KS_Z);
        gemm_bf16<0,false,true><<<grid, 256, GSMEM_BYTES>>>(
            p_xnb, 3*DMODEL, p_ipb + (size_t)DINNER * 3*DMODEL, 3*DMODEL, nullptr,
            p_zp, DINNER, NOUT, DINNER, (3*DMODEL)/KS_Z);
    }
    k_redsum<<<(NOUT*DINNER + 255)/256, 256>>>(p_zp, p_z, NOUT*DINNER, KS_Z, NOUT*DINNER);

    // conv + silu + split
    k_conv<<<(NROWS*DINNER + 255)/256, 256>>>(conv_w, conv_b);

    // x_proj split-K=8: dbcp[s][1568,96]
    k_wsplit<<<(96*2048 + 255)/256, 256>>>(x_proj, p_xpb, 96, 2048);
    {
        dim3 grid(1, (NROWS + 127)/128, KS_XP);
        gemm_bf16<0,false,false><<<grid, 256, GSMEM_BYTES>>>(
            p_xcb, 3*DINNER, p_xpb, 3*DINNER, nullptr,
            p_dbcp, 96, NROWS, 96, (3*DINNER)/KS_XP);
    }
    k_redsum<<<(NROWS*96 + 255)/256, 256>>>(p_dbcp, p_dbc, NROWS*96, KS_XP, NROWS*96);

    // dt input split + dt_proj: dlt = softplus(dtb @ dtwb^T + dt_b)  (K' = 192)
    k_wsplit<<<(2048*64 + 255)/256, 256>>>(dt_w, p_dtwb, 2048, 64);
    k_asplit<<<(NROWS*64 + 255)/256, 256>>>(p_dbc, 96, p_dtb, NROWS, 64);
    {
        dim3 grid(2048/128, (NROWS + 127)/128, 1);
        gemm_bf16<2,true,false><<<grid, 256, GSMEM_BYTES>>>(
            p_dtb, 3*DTRANK, p_dtwb, 3*DTRANK, dt_b,
            p_dlt, DINNER, NROWS, DINNER, 3*DTRANK);
    }

    // selective scan (writes bf16 split g_ycb directly)
    k_scan<<<(BB*DINNER*16 + 255)/256, 256>>>(A_log, Dp);

    // out_proj split-K=4: mop[s][784,1024] = ycb-slice @ opb-slice^T
    k_wsplit<<<(1024*2048 + 255)/256, 256>>>(out_proj, p_opb, 1024, 2048);
    {
        dim3 grid(1024/128, (NOUT + 127)/128, KS_OP);
        gemm_bf16<0,false,false><<<grid, 256, GSMEM_BYTES>>>(
            p_ycb, 3*DINNER, p_opb, 3*DINNER, nullptr,
            p_mop, DMODEL, NOUT, DMODEL, (3*DINNER)/KS_OP);
    }

    // residual + partial-sum + final LN -> d_out
    k_final<<<NOUT, 256>>>(ln_g, ln_b, out);
}